// round 10
// baseline (speedup 1.0000x reference)
#include <cuda_runtime.h>
#include <cuda_bf16.h>
#include <cstdint>

#define NN 50000
#define NE 800000
#define NG 64
#define NF 11
#define EF 14
#define HH 128
#define PP 128
#define NL 3
#define BN_EPS 1e-5f

#define NE_BLOCKS 1563          // node-embed blocks (32 nodes each)
#define HIST_BLOCKS 1563        // hist blocks (512 edges each)
#define FUSED_GRID (NE_BLOCKS + HIST_BLOCKS + 3)

// ---------------- scratch (__device__ globals; device-code references only) --
// Invariant: g_cnt, g_pool, g_gcnt are ZERO on entry (re-zeroed by cleanup).
__device__ float g_h[NN * HH];
__device__ float g_z[NN * HH];
__device__ float g_t[NN * HH];
__device__ float g_e[(size_t)NE * HH];   // edge embeddings, CSR order (410MB)
__device__ int   g_cnt[NN];
__device__ int   g_row[NN + 1];
__device__ int   g_cur[NN];
__device__ int   g_src[NE];
__device__ float g_scale[NL * HH];
__device__ float g_shift[NL * HH];
__device__ float g_pool[NG * HH];
__device__ float g_gcnt[NG];

// ---------------- launch #1: node_embed + edge histogram + BN fold ----------
__global__ void __launch_bounds__(128) fused_front(const float* __restrict__ x,
                                                   const float* __restrict__ nW,
                                                   const float* __restrict__ nb,
                                                   const int* __restrict__ ei,
                                                   const float* __restrict__ lin1_b,
                                                   const float* __restrict__ gamma,
                                                   const float* __restrict__ beta,
                                                   const float* __restrict__ mean,
                                                   const float* __restrict__ var) {
    int b = blockIdx.x;
    int t = threadIdx.x;
    if (b < NE_BLOCKS) {
        __shared__ float xs[32 * NF];
        float w[NF];
#pragma unroll
        for (int k = 0; k < NF; k++) w[k] = nW[t * NF + k];
        float bias = nb[t];
        int base = b * 32;
        for (int i = t; i < 32 * NF; i += 128) {
            int node = base + i / NF;
            xs[i] = (node < NN) ? x[node * NF + i % NF] : 0.f;
        }
        __syncthreads();
        for (int j = 0; j < 32; j++) {
            int node = base + j;
            if (node >= NN) break;
            float acc = bias;
#pragma unroll
            for (int k = 0; k < NF; k++) acc = fmaf(xs[j * NF + k], w[k], acc);
            g_h[node * HH + t] = acc;
        }
    } else if (b < NE_BLOCKS + HIST_BLOCKS) {
        int base = (b - NE_BLOCKS) * 512;
#pragma unroll
        for (int r = 0; r < 4; r++) {
            int i = base + r * 128 + t;
            if (i < NE) atomicAdd(&g_cnt[ei[NE + i]], 1);
        }
    } else {
        int i = (b - NE_BLOCKS - HIST_BLOCKS) * 128 + t;
        if (i < NL * HH) {
            float sc = gamma[i] * rsqrtf(var[i] + BN_EPS);
            g_scale[i] = sc;
            g_shift[i] = (lin1_b[i] - mean[i]) * sc + beta[i];
        }
    }
}

// ---------------- launch #2: single-block scan ------------------------------
__global__ void __launch_bounds__(1024) scan_kernel() {
    __shared__ int partial[1024];
    const int CH = (NN + 1023) / 1024;   // 49
    int t = threadIdx.x;
    int beg = t * CH;
    int sum = 0;
    for (int i = 0; i < CH; i++) {
        int idx = beg + i;
        if (idx < NN) sum += g_cnt[idx];
    }
    partial[t] = sum;
    __syncthreads();
    for (int off = 1; off < 1024; off <<= 1) {
        int v = (t >= off) ? partial[t - off] : 0;
        __syncthreads();
        partial[t] += v;
        __syncthreads();
    }
    int run = (t > 0) ? partial[t - 1] : 0;
    for (int i = 0; i < CH; i++) {
        int idx = beg + i;
        if (idx < NN) {
            g_row[idx] = run;
            g_cur[idx] = run;
            run += g_cnt[idx];
        }
    }
    if (t == 1023) g_row[NN] = run;
}

// ---------------- launch #3: fused scatter + edge embedding -----------------
__global__ void __launch_bounds__(128) edge_embed(const int* __restrict__ ei,
                                                  const float* __restrict__ ea,
                                                  const float* __restrict__ eW,
                                                  const float* __restrict__ eB) {
    __shared__ float es[64 * EF];
    __shared__ int pos[64];
    int t = threadIdx.x;
    int base = blockIdx.x * 64;

    if (t < 64) {
        int e = base + t;
        if (e < NE) {
            int d = ei[NE + e];
            int p = atomicAdd(&g_cur[d], 1);
            pos[t] = p;
            g_src[p] = ei[e];
        }
    }
    float w[EF];
#pragma unroll
    for (int k = 0; k < EF; k++) w[k] = eW[t * EF + k];
    float bias = eB[t];
    for (int i = t; i < 64 * EF; i += 128) {
        int e = base + i / EF;
        es[i] = (e < NE) ? ea[(size_t)e * EF + i % EF] : 0.f;
    }
    __syncthreads();
    int lim = NE - base; if (lim > 64) lim = 64;
    for (int j = 0; j < lim; j++) {
        float acc = bias;
#pragma unroll
        for (int k = 0; k < EF; k++) acc = fmaf(es[j * EF + k], w[k], acc);
        g_e[(size_t)pos[j] * HH + t] = acc;
    }
}

// ---------------- launch #4 (PROFILED): streaming GINE aggregation ----------
__global__ void __launch_bounds__(256) aggregate_kernel() {
    int gid = blockIdx.x * blockDim.x + threadIdx.x;
    int node = gid >> 5;
    if (node >= NN) return;
    int lane = gid & 31;
    const float4* hp = (const float4*)g_h;
    const float4* ep = (const float4*)g_e;
    float4 accA = make_float4(0.f, 0.f, 0.f, 0.f);
    float4 accB = make_float4(0.f, 0.f, 0.f, 0.f);
    int beg = g_row[node], end = g_row[node + 1];
    int i = beg;
    for (; i + 2 <= end; i += 2) {
        int s0 = __ldg(&g_src[i]);
        int s1 = __ldg(&g_src[i + 1]);
        float4 e0 = ep[(size_t)i * 32 + lane];
        float4 e1 = ep[(size_t)(i + 1) * 32 + lane];
        float4 h0 = hp[s0 * 32 + lane];
        float4 h1 = hp[s1 * 32 + lane];
        accA.x += fmaxf(h0.x + e0.x, 0.f);  accB.x += fmaxf(h1.x + e1.x, 0.f);
        accA.y += fmaxf(h0.y + e0.y, 0.f);  accB.y += fmaxf(h1.y + e1.y, 0.f);
        accA.z += fmaxf(h0.z + e0.z, 0.f);  accB.z += fmaxf(h1.z + e1.z, 0.f);
        accA.w += fmaxf(h0.w + e0.w, 0.f);  accB.w += fmaxf(h1.w + e1.w, 0.f);
    }
    if (i < end) {
        int s0 = __ldg(&g_src[i]);
        float4 e0 = ep[(size_t)i * 32 + lane];
        float4 h0 = hp[s0 * 32 + lane];
        accA.x += fmaxf(h0.x + e0.x, 0.f);
        accA.y += fmaxf(h0.y + e0.y, 0.f);
        accA.z += fmaxf(h0.z + e0.z, 0.f);
        accA.w += fmaxf(h0.w + e0.w, 0.f);
    }
    float4 hv = hp[node * 32 + lane];
    accA.x += accB.x + hv.x;
    accA.y += accB.y + hv.y;
    accA.z += accB.z + hv.z;
    accA.w += accB.w + hv.w;
    ((float4*)g_z)[node * 32 + lane] = accA;
}

// ---------------- SGEMM: C[128 x 128], K=128, double-buffered chunks of 32 --
#define AL 132
#define WL 132
#define BUF_FLOATS (32 * (AL + WL))                 // one buffer (As+Ws)
#define GEMM_SMEM_BYTES (2 * BUF_FLOATS * 4)        // 67584 bytes

__device__ __forceinline__ void load_chunk(const float* __restrict__ A,
                                           const float* __restrict__ W,
                                           float* As, float* Ws,
                                           int rowbase, int kc, int t) {
    const float4* A4 = (const float4*)A;
    const float4* W4 = (const float4*)W;
    int kq4 = kc >> 2;
#pragma unroll
    for (int r = 0; r < 4; r++) {
        int idx = t + 256 * r;
        int m = idx >> 3;
        int kq = idx & 7;
        int row = rowbase + m;
        float4 v = make_float4(0.f, 0.f, 0.f, 0.f);
        if (row < NN) v = A4[row * 32 + kq4 + kq];
        As[(kq * 4 + 0) * AL + m] = v.x;
        As[(kq * 4 + 1) * AL + m] = v.y;
        As[(kq * 4 + 2) * AL + m] = v.z;
        As[(kq * 4 + 3) * AL + m] = v.w;
        float4 wv = W4[m * 32 + kq4 + kq];
        Ws[(kq * 4 + 0) * WL + m] = wv.x;
        Ws[(kq * 4 + 1) * WL + m] = wv.y;
        Ws[(kq * 4 + 2) * WL + m] = wv.z;
        Ws[(kq * 4 + 3) * WL + m] = wv.w;
    }
}

__device__ __forceinline__ void gemm_accum(const float* As, const float* Ws,
                                           int m0, int n0, float acc[8][8]) {
#pragma unroll
    for (int k = 0; k < 32; k++) {
        float4 a0 = *(const float4*)&As[k * AL + m0];
        float4 a1 = *(const float4*)&As[k * AL + m0 + 4];
        float4 b0 = *(const float4*)&Ws[k * WL + n0];
        float4 b1 = *(const float4*)&Ws[k * WL + n0 + 4];
        float a[8] = {a0.x, a0.y, a0.z, a0.w, a1.x, a1.y, a1.z, a1.w};
        float b[8] = {b0.x, b0.y, b0.z, b0.w, b1.x, b1.y, b1.z, b1.w};
#pragma unroll
        for (int j = 0; j < 8; j++)
#pragma unroll
            for (int i = 0; i < 8; i++) acc[j][i] = fmaf(a[j], b[i], acc[j][i]);
    }
}

// double-buffered mainloop shared by both passes
__device__ __forceinline__ void gemm_main(const float* __restrict__ A,
                                          const float* __restrict__ W,
                                          float* sm, int rowbase, int t,
                                          int m0, int n0, float acc[8][8]) {
    float* As[2] = {sm, sm + BUF_FLOATS};
    float* Ws[2] = {sm + 32 * AL, sm + BUF_FLOATS + 32 * AL};
    load_chunk(A, W, As[0], Ws[0], rowbase, 0, t);
    __syncthreads();
#pragma unroll
    for (int c = 0; c < 4; c++) {
        int cur = c & 1, nxt = cur ^ 1;
        if (c < 3) load_chunk(A, W, As[nxt], Ws[nxt], rowbase, (c + 1) * 32, t);
        gemm_accum(As[cur], Ws[cur], m0, n0, acc);
        __syncthreads();
    }
}

// pass 1: g_t = relu(scale[li] * (g_z @ W1^T) + shift[li])
__global__ void __launch_bounds__(256, 2) gemm1_kernel(const float* __restrict__ W1,
                                                       int li) {
    extern __shared__ float sm[];
    int t = threadIdx.x;
    int m0 = (t >> 4) * 8;
    int n0 = (t & 15) * 8;
    int rowbase = blockIdx.x * 128;

    float acc[8][8];
#pragma unroll
    for (int j = 0; j < 8; j++)
#pragma unroll
        for (int i = 0; i < 8; i++) acc[j][i] = 0.f;

    gemm_main(g_z, W1, sm, rowbase, t, m0, n0, acc);

    float sc[8], sh[8];
#pragma unroll
    for (int i = 0; i < 8; i++) {
        sc[i] = g_scale[li * HH + n0 + i];
        sh[i] = g_shift[li * HH + n0 + i];
    }
#pragma unroll
    for (int j = 0; j < 8; j++) {
        int row = rowbase + m0 + j;
        if (row < NN) {
            float o[8];
#pragma unroll
            for (int i = 0; i < 8; i++) o[i] = fmaxf(fmaf(acc[j][i], sc[i], sh[i]), 0.f);
            *(float4*)&g_t[row * 128 + n0]     = make_float4(o[0], o[1], o[2], o[3]);
            *(float4*)&g_t[row * 128 + n0 + 4] = make_float4(o[4], o[5], o[6], o[7]);
        }
    }
}

// pass 2: g_h = relu(g_t @ W2^T + b2) + g_h
__global__ void __launch_bounds__(256, 2) gemm2_kernel(const float* __restrict__ W2,
                                                       const float* __restrict__ b2) {
    extern __shared__ float sm[];
    int t = threadIdx.x;
    int m0 = (t >> 4) * 8;
    int n0 = (t & 15) * 8;
    int rowbase = blockIdx.x * 128;

    float acc[8][8];
#pragma unroll
    for (int j = 0; j < 8; j++)
#pragma unroll
        for (int i = 0; i < 8; i++) acc[j][i] = 0.f;

    gemm_main(g_t, W2, sm, rowbase, t, m0, n0, acc);

    float bias[8];
#pragma unroll
    for (int i = 0; i < 8; i++) bias[i] = b2[n0 + i];
#pragma unroll
    for (int j = 0; j < 8; j++) {
        int row = rowbase + m0 + j;
        if (row < NN) {
            float4 h0 = *(const float4*)&g_h[row * 128 + n0];
            float4 h1 = *(const float4*)&g_h[row * 128 + n0 + 4];
            float4 o0, o1;
            o0.x = fmaxf(acc[j][0] + bias[0], 0.f) + h0.x;
            o0.y = fmaxf(acc[j][1] + bias[1], 0.f) + h0.y;
            o0.z = fmaxf(acc[j][2] + bias[2], 0.f) + h0.z;
            o0.w = fmaxf(acc[j][3] + bias[3], 0.f) + h0.w;
            o1.x = fmaxf(acc[j][4] + bias[4], 0.f) + h1.x;
            o1.y = fmaxf(acc[j][5] + bias[5], 0.f) + h1.y;
            o1.z = fmaxf(acc[j][6] + bias[6], 0.f) + h1.z;
            o1.w = fmaxf(acc[j][7] + bias[7], 0.f) + h1.w;
            *(float4*)&g_h[row * 128 + n0]     = o0;
            *(float4*)&g_h[row * 128 + n0 + 4] = o1;
        }
    }
}

// ---------------- pooling ----------------------------------------------------
__global__ void __launch_bounds__(128) pool_kernel(const int* __restrict__ batch) {
    int t = threadIdx.x;
    int base = blockIdx.x * 128;
    float acc = 0.f, runc = 0.f;
    int cur = -1;
    for (int j = 0; j < 128; j++) {
        int node = base + j;
        if (node >= NN) break;
        int g = batch[node];
        if (g != cur) {
            if (cur >= 0) {
                atomicAdd(&g_pool[cur * 128 + t], acc);
                if (t == 0) atomicAdd(&g_gcnt[cur], runc);
            }
            cur = g; acc = 0.f; runc = 0.f;
        }
        acc += g_h[node * 128 + t];
        runc += 1.f;
    }
    if (cur >= 0) {
        atomicAdd(&g_pool[cur * 128 + t], acc);
        if (t == 0) atomicAdd(&g_gcnt[cur], runc);
    }
}

// ---------------- final projection ------------------------------------------
__global__ void __launch_bounds__(128) proj_kernel(const float* __restrict__ pW,
                                                   const float* __restrict__ pb,
                                                   float* __restrict__ out) {
    __shared__ float pr[128];
    int g = blockIdx.x, t = threadIdx.x;
    float c = fmaxf(g_gcnt[g], 1.f);
    pr[t] = g_pool[g * 128 + t] / c;
    __syncthreads();
    float acc = pb[t];
#pragma unroll 4
    for (int h = 0; h < 128; h++) acc = fmaf(pr[h], pW[t * 128 + h], acc);
    out[g * 128 + t] = acc;
}

// ---------------- cleanup: restore zero-invariant for next call -------------
__global__ void __launch_bounds__(256) cleanup_kernel() {
    int i = blockIdx.x * blockDim.x + threadIdx.x;
    if (i < NN) g_cnt[i] = 0;
    if (i < NG * HH) g_pool[i] = 0.f;
    if (i < NG) g_gcnt[i] = 0.f;
}

// ---------------- launch ------------------------------------------------------
extern "C" void kernel_launch(void* const* d_in, const int* in_sizes, int n_in,
                              void* d_out, int out_size) {
    const float* x       = (const float*)d_in[0];
    const int*   ei      = (const int*)  d_in[1];
    const float* ea      = (const float*)d_in[2];
    const int*   batch   = (const int*)  d_in[3];
    const float* node_W  = (const float*)d_in[4];
    const float* node_b  = (const float*)d_in[5];
    const float* edge_W  = (const float*)d_in[6];
    const float* edge_b  = (const float*)d_in[7];
    const float* lin1_W  = (const float*)d_in[8];
    const float* lin1_b  = (const float*)d_in[9];
    const float* bn_g    = (const float*)d_in[10];
    const float* bn_b    = (const float*)d_in[11];
    const float* bn_m    = (const float*)d_in[12];
    const float* bn_v    = (const float*)d_in[13];
    const float* lin2_W  = (const float*)d_in[14];
    const float* lin2_b  = (const float*)d_in[15];
    const float* proj_W  = (const float*)d_in[16];
    const float* proj_b  = (const float*)d_in[17];
    float* out = (float*)d_out;

    static bool attr_done = false;
    if (!attr_done) {
        cudaFuncSetAttribute(gemm1_kernel,
                             cudaFuncAttributeMaxDynamicSharedMemorySize,
                             GEMM_SMEM_BYTES);
        cudaFuncSetAttribute(gemm2_kernel,
                             cudaFuncAttributeMaxDynamicSharedMemorySize,
                             GEMM_SMEM_BYTES);
        attr_done = true;
    }

    fused_front<<<FUSED_GRID, 128>>>(x, node_W, node_b, ei,
                                     lin1_b, bn_g, bn_b, bn_m, bn_v);
    scan_kernel<<<1, 1024>>>();
    edge_embed<<<(NE + 63) / 64, 128>>>(ei, ea, edge_W, edge_b);

    const int gemm_grid = (NN + 127) / 128;
    for (int li = 0; li < NL; li++) {
        // #4 (li==0) -> profiled control: should stay ~89us
        aggregate_kernel<<<(NN * 32 + 255) / 256, 256>>>();
        gemm1_kernel<<<gemm_grid, 256, GEMM_SMEM_BYTES>>>(lin1_W + li * HH * HH, li);
        gemm2_kernel<<<gemm_grid, 256, GEMM_SMEM_BYTES>>>(lin2_W + li * HH * HH,
                                                          lin2_b + li * HH);
    }

    pool_kernel<<<(NN + 127) / 128, 128>>>(batch);
    proj_kernel<<<NG, 128>>>(proj_W, proj_b, out);
    cleanup_kernel<<<(NN + 255) / 256, 256>>>();
}

// round 12
// speedup vs baseline: 1.3213x; 1.3213x over previous
#include <cuda_runtime.h>
#include <cuda_fp16.h>
#include <cstdint>

#define NN 50000
#define NE 800000
#define NG 64
#define NF 11
#define EF 14
#define HH 128
#define PP 128
#define NL 3
#define BN_EPS 1e-5f

#define NE_BLOCKS 1563          // node-embed blocks (32 nodes each)
#define HIST_BLOCKS 1563        // hist blocks (512 edges each)
#define FUSED_GRID (NE_BLOCKS + HIST_BLOCKS + 3)

// ---------------- scratch (__device__ globals; device-code references only) --
// Invariant: g_cnt, g_pool, g_gcnt are ZERO on entry (re-zeroed by cleanup).
__device__ float  g_h[NN * HH];
__device__ float  g_z[NN * HH];
__device__ float  g_t[NN * HH];
__device__ __half g_e[(size_t)NE * HH];  // edge embeddings, CSR order, fp16 (205MB)
__device__ int    g_cnt[NN];
__device__ int    g_row[NN + 1];
__device__ int    g_cur[NN];
__device__ int    g_src[NE];
__device__ float  g_scale[NL * HH];
__device__ float  g_shift[NL * HH];
__device__ float  g_pool[NG * HH];
__device__ float  g_gcnt[NG];

// ---------------- launch #1: node_embed + edge histogram + BN fold ----------
__global__ void __launch_bounds__(128) fused_front(const float* __restrict__ x,
                                                   const float* __restrict__ nW,
                                                   const float* __restrict__ nb,
                                                   const int* __restrict__ ei,
                                                   const float* __restrict__ lin1_b,
                                                   const float* __restrict__ gamma,
                                                   const float* __restrict__ beta,
                                                   const float* __restrict__ mean,
                                                   const float* __restrict__ var) {
    int b = blockIdx.x;
    int t = threadIdx.x;
    if (b < NE_BLOCKS) {
        __shared__ float xs[32 * NF];
        float w[NF];
#pragma unroll
        for (int k = 0; k < NF; k++) w[k] = nW[t * NF + k];
        float bias = nb[t];
        int base = b * 32;
        for (int i = t; i < 32 * NF; i += 128) {
            int node = base + i / NF;
            xs[i] = (node < NN) ? x[node * NF + i % NF] : 0.f;
        }
        __syncthreads();
        for (int j = 0; j < 32; j++) {
            int node = base + j;
            if (node >= NN) break;
            float acc = bias;
#pragma unroll
            for (int k = 0; k < NF; k++) acc = fmaf(xs[j * NF + k], w[k], acc);
            g_h[node * HH + t] = acc;
        }
    } else if (b < NE_BLOCKS + HIST_BLOCKS) {
        int base = (b - NE_BLOCKS) * 512;
#pragma unroll
        for (int r = 0; r < 4; r++) {
            int i = base + r * 128 + t;
            if (i < NE) atomicAdd(&g_cnt[ei[NE + i]], 1);
        }
    } else {
        int i = (b - NE_BLOCKS - HIST_BLOCKS) * 128 + t;
        if (i < NL * HH) {
            float sc = gamma[i] * rsqrtf(var[i] + BN_EPS);
            g_scale[i] = sc;
            g_shift[i] = (lin1_b[i] - mean[i]) * sc + beta[i];
        }
    }
}

// ---------------- launch #2: single-block scan ------------------------------
__global__ void __launch_bounds__(1024) scan_kernel() {
    __shared__ int partial[1024];
    const int CH = (NN + 1023) / 1024;   // 49
    int t = threadIdx.x;
    int beg = t * CH;
    int sum = 0;
    for (int i = 0; i < CH; i++) {
        int idx = beg + i;
        if (idx < NN) sum += g_cnt[idx];
    }
    partial[t] = sum;
    __syncthreads();
    for (int off = 1; off < 1024; off <<= 1) {
        int v = (t >= off) ? partial[t - off] : 0;
        __syncthreads();
        partial[t] += v;
        __syncthreads();
    }
    int run = (t > 0) ? partial[t - 1] : 0;
    for (int i = 0; i < CH; i++) {
        int idx = beg + i;
        if (idx < NN) {
            g_row[idx] = run;
            g_cur[idx] = run;
            run += g_cnt[idx];
        }
    }
    if (t == 1023) g_row[NN] = run;
}

// ---------------- launch #3: fused scatter + edge embedding (fp16 out) ------
__global__ void __launch_bounds__(128) edge_embed(const int* __restrict__ ei,
                                                  const float* __restrict__ ea,
                                                  const float* __restrict__ eW,
                                                  const float* __restrict__ eB) {
    __shared__ float es[64 * EF];
    __shared__ int pos[64];
    int t = threadIdx.x;
    int base = blockIdx.x * 64;

    if (t < 64) {
        int e = base + t;
        if (e < NE) {
            int d = ei[NE + e];
            int p = atomicAdd(&g_cur[d], 1);
            pos[t] = p;
            g_src[p] = ei[e];
        }
    }
    float w[EF];
#pragma unroll
    for (int k = 0; k < EF; k++) w[k] = eW[t * EF + k];
    float bias = eB[t];
    for (int i = t; i < 64 * EF; i += 128) {
        int e = base + i / EF;
        es[i] = (e < NE) ? ea[(size_t)e * EF + i % EF] : 0.f;
    }
    __syncthreads();
    int lim = NE - base; if (lim > 64) lim = 64;
    for (int j = 0; j < lim; j++) {
        float acc = bias;
#pragma unroll
        for (int k = 0; k < EF; k++) acc = fmaf(es[j * EF + k], w[k], acc);
        g_e[(size_t)pos[j] * HH + t] = __float2half_rn(acc);
    }
}

// ---------------- launch #4 (PROFILED): streaming GINE aggregation ----------
// z = h + sum_j relu(h[src] + e); warp/node; e read sequentially (fp16, 8B/lane).
__device__ __forceinline__ float4 half4_to_float4(uint2 v) {
    __half2 p0 = *reinterpret_cast<__half2*>(&v.x);
    __half2 p1 = *reinterpret_cast<__half2*>(&v.y);
    float2 f0 = __half22float2(p0);
    float2 f1 = __half22float2(p1);
    return make_float4(f0.x, f0.y, f1.x, f1.y);
}

__global__ void __launch_bounds__(256) aggregate_kernel() {
    int gid = blockIdx.x * blockDim.x + threadIdx.x;
    int node = gid >> 5;
    if (node >= NN) return;
    int lane = gid & 31;
    const float4* hp = (const float4*)g_h;
    const uint2* ep = (const uint2*)g_e;   // 8B = 4 halfs per lane
    float4 accA = make_float4(0.f, 0.f, 0.f, 0.f);
    float4 accB = make_float4(0.f, 0.f, 0.f, 0.f);
    int beg = g_row[node], end = g_row[node + 1];
    int i = beg;
    for (; i + 2 <= end; i += 2) {
        int s0 = __ldg(&g_src[i]);
        int s1 = __ldg(&g_src[i + 1]);
        float4 e0 = half4_to_float4(ep[(size_t)i * 32 + lane]);
        float4 e1 = half4_to_float4(ep[(size_t)(i + 1) * 32 + lane]);
        float4 h0 = hp[s0 * 32 + lane];
        float4 h1 = hp[s1 * 32 + lane];
        accA.x += fmaxf(h0.x + e0.x, 0.f);  accB.x += fmaxf(h1.x + e1.x, 0.f);
        accA.y += fmaxf(h0.y + e0.y, 0.f);  accB.y += fmaxf(h1.y + e1.y, 0.f);
        accA.z += fmaxf(h0.z + e0.z, 0.f);  accB.z += fmaxf(h1.z + e1.z, 0.f);
        accA.w += fmaxf(h0.w + e0.w, 0.f);  accB.w += fmaxf(h1.w + e1.w, 0.f);
    }
    if (i < end) {
        int s0 = __ldg(&g_src[i]);
        float4 e0 = half4_to_float4(ep[(size_t)i * 32 + lane]);
        float4 h0 = hp[s0 * 32 + lane];
        accA.x += fmaxf(h0.x + e0.x, 0.f);
        accA.y += fmaxf(h0.y + e0.y, 0.f);
        accA.z += fmaxf(h0.z + e0.z, 0.f);
        accA.w += fmaxf(h0.w + e0.w, 0.f);
    }
    float4 hv = hp[node * 32 + lane];
    accA.x += accB.x + hv.x;
    accA.y += accB.y + hv.y;
    accA.z += accB.z + hv.z;
    accA.w += accB.w + hv.w;
    ((float4*)g_z)[node * 32 + lane] = accA;
}

// ---------------- SGEMM (R7 config): C[128 x 128], K=128, chunks of 32 ------
#define AL 132
#define WL 132

__device__ __forceinline__ void load_chunk(const float* __restrict__ A,
                                           const float* __restrict__ W,
                                           float* As, float* Ws,
                                           int rowbase, int kc, int t) {
    const float4* A4 = (const float4*)A;
    const float4* W4 = (const float4*)W;
    int kq4 = kc >> 2;
#pragma unroll
    for (int r = 0; r < 4; r++) {
        int idx = t + 256 * r;
        int m = idx >> 3;
        int kq = idx & 7;
        int row = rowbase + m;
        float4 v = make_float4(0.f, 0.f, 0.f, 0.f);
        if (row < NN) v = A4[row * 32 + kq4 + kq];
        As[(kq * 4 + 0) * AL + m] = v.x;
        As[(kq * 4 + 1) * AL + m] = v.y;
        As[(kq * 4 + 2) * AL + m] = v.z;
        As[(kq * 4 + 3) * AL + m] = v.w;
        float4 wv = W4[m * 32 + kq4 + kq];
        Ws[(kq * 4 + 0) * WL + m] = wv.x;
        Ws[(kq * 4 + 1) * WL + m] = wv.y;
        Ws[(kq * 4 + 2) * WL + m] = wv.z;
        Ws[(kq * 4 + 3) * WL + m] = wv.w;
    }
}

__device__ __forceinline__ void gemm_accum(const float* As, const float* Ws,
                                           int m0, int n0, float acc[8][8]) {
#pragma unroll
    for (int k = 0; k < 32; k++) {
        float4 a0 = *(const float4*)&As[k * AL + m0];
        float4 a1 = *(const float4*)&As[k * AL + m0 + 4];
        float4 b0 = *(const float4*)&Ws[k * WL + n0];
        float4 b1 = *(const float4*)&Ws[k * WL + n0 + 4];
        float a[8] = {a0.x, a0.y, a0.z, a0.w, a1.x, a1.y, a1.z, a1.w};
        float b[8] = {b0.x, b0.y, b0.z, b0.w, b1.x, b1.y, b1.z, b1.w};
#pragma unroll
        for (int j = 0; j < 8; j++)
#pragma unroll
            for (int i = 0; i < 8; i++) acc[j][i] = fmaf(a[j], b[i], acc[j][i]);
    }
}

// pass 1: g_t = relu(scale[li] * (g_z @ W1^T) + shift[li])
__global__ void __launch_bounds__(256) gemm1_kernel(const float* __restrict__ W1,
                                                    int li) {
    __shared__ float As[32 * AL];
    __shared__ float Ws[32 * WL];
    int t = threadIdx.x;
    int m0 = (t >> 4) * 8;
    int n0 = (t & 15) * 8;
    int rowbase = blockIdx.x * 128;

    float acc[8][8];
#pragma unroll
    for (int j = 0; j < 8; j++)
#pragma unroll
        for (int i = 0; i < 8; i++) acc[j][i] = 0.f;

    for (int kc = 0; kc < 128; kc += 32) {
        load_chunk(g_z, W1, As, Ws, rowbase, kc, t);
        __syncthreads();
        gemm_accum(As, Ws, m0, n0, acc);
        __syncthreads();
    }

    float sc[8], sh[8];
#pragma unroll
    for (int i = 0; i < 8; i++) {
        sc[i] = g_scale[li * HH + n0 + i];
        sh[i] = g_shift[li * HH + n0 + i];
    }
#pragma unroll
    for (int j = 0; j < 8; j++) {
        int row = rowbase + m0 + j;
        if (row < NN) {
            float o[8];
#pragma unroll
            for (int i = 0; i < 8; i++) o[i] = fmaxf(fmaf(acc[j][i], sc[i], sh[i]), 0.f);
            *(float4*)&g_t[row * 128 + n0]     = make_float4(o[0], o[1], o[2], o[3]);
            *(float4*)&g_t[row * 128 + n0 + 4] = make_float4(o[4], o[5], o[6], o[7]);
        }
    }
}

// pass 2: g_h = relu(g_t @ W2^T + b2) + g_h
__global__ void __launch_bounds__(256) gemm2_kernel(const float* __restrict__ W2,
                                                    const float* __restrict__ b2) {
    __shared__ float As[32 * AL];
    __shared__ float Ws[32 * WL];
    int t = threadIdx.x;
    int m0 = (t >> 4) * 8;
    int n0 = (t & 15) * 8;
    int rowbase = blockIdx.x * 128;

    float acc[8][8];
#pragma unroll
    for (int j = 0; j < 8; j++)
#pragma unroll
        for (int i = 0; i < 8; i++) acc[j][i] = 0.f;

    for (int kc = 0; kc < 128; kc += 32) {
        load_chunk(g_t, W2, As, Ws, rowbase, kc, t);
        __syncthreads();
        gemm_accum(As, Ws, m0, n0, acc);
        __syncthreads();
    }

    float bias[8];
#pragma unroll
    for (int i = 0; i < 8; i++) bias[i] = b2[n0 + i];
#pragma unroll
    for (int j = 0; j < 8; j++) {
        int row = rowbase + m0 + j;
        if (row < NN) {
            float4 h0 = *(const float4*)&g_h[row * 128 + n0];
            float4 h1 = *(const float4*)&g_h[row * 128 + n0 + 4];
            float4 o0, o1;
            o0.x = fmaxf(acc[j][0] + bias[0], 0.f) + h0.x;
            o0.y = fmaxf(acc[j][1] + bias[1], 0.f) + h0.y;
            o0.z = fmaxf(acc[j][2] + bias[2], 0.f) + h0.z;
            o0.w = fmaxf(acc[j][3] + bias[3], 0.f) + h0.w;
            o1.x = fmaxf(acc[j][4] + bias[4], 0.f) + h1.x;
            o1.y = fmaxf(acc[j][5] + bias[5], 0.f) + h1.y;
            o1.z = fmaxf(acc[j][6] + bias[6], 0.f) + h1.z;
            o1.w = fmaxf(acc[j][7] + bias[7], 0.f) + h1.w;
            *(float4*)&g_h[row * 128 + n0]     = o0;
            *(float4*)&g_h[row * 128 + n0 + 4] = o1;
        }
    }
}

// ---------------- pooling ----------------------------------------------------
__global__ void __launch_bounds__(128) pool_kernel(const int* __restrict__ batch) {
    int t = threadIdx.x;
    int base = blockIdx.x * 128;
    float acc = 0.f, runc = 0.f;
    int cur = -1;
    for (int j = 0; j < 128; j++) {
        int node = base + j;
        if (node >= NN) break;
        int g = batch[node];
        if (g != cur) {
            if (cur >= 0) {
                atomicAdd(&g_pool[cur * 128 + t], acc);
                if (t == 0) atomicAdd(&g_gcnt[cur], runc);
            }
            cur = g; acc = 0.f; runc = 0.f;
        }
        acc += g_h[node * 128 + t];
        runc += 1.f;
    }
    if (cur >= 0) {
        atomicAdd(&g_pool[cur * 128 + t], acc);
        if (t == 0) atomicAdd(&g_gcnt[cur], runc);
    }
}

// ---------------- final projection ------------------------------------------
__global__ void __launch_bounds__(128) proj_kernel(const float* __restrict__ pW,
                                                   const float* __restrict__ pb,
                                                   float* __restrict__ out) {
    __shared__ float pr[128];
    int g = blockIdx.x, t = threadIdx.x;
    float c = fmaxf(g_gcnt[g], 1.f);
    pr[t] = g_pool[g * 128 + t] / c;
    __syncthreads();
    float acc = pb[t];
#pragma unroll 4
    for (int h = 0; h < 128; h++) acc = fmaf(pr[h], pW[t * 128 + h], acc);
    out[g * 128 + t] = acc;
}

// ---------------- cleanup: restore zero-invariant for next call -------------
__global__ void __launch_bounds__(256) cleanup_kernel() {
    int i = blockIdx.x * blockDim.x + threadIdx.x;
    if (i < NN) g_cnt[i] = 0;
    if (i < NG * HH) g_pool[i] = 0.f;
    if (i < NG) g_gcnt[i] = 0.f;
}

// ---------------- launch ------------------------------------------------------
extern "C" void kernel_launch(void* const* d_in, const int* in_sizes, int n_in,
                              void* d_out, int out_size) {
    const float* x       = (const float*)d_in[0];
    const int*   ei      = (const int*)  d_in[1];
    const float* ea      = (const float*)d_in[2];
    const int*   batch   = (const int*)  d_in[3];
    const float* node_W  = (const float*)d_in[4];
    const float* node_b  = (const float*)d_in[5];
    const float* edge_W  = (const float*)d_in[6];
    const float* edge_b  = (const float*)d_in[7];
    const float* lin1_W  = (const float*)d_in[8];
    const float* lin1_b  = (const float*)d_in[9];
    const float* bn_g    = (const float*)d_in[10];
    const float* bn_b    = (const float*)d_in[11];
    const float* bn_m    = (const float*)d_in[12];
    const float* bn_v    = (const float*)d_in[13];
    const float* lin2_W  = (const float*)d_in[14];
    const float* lin2_b  = (const float*)d_in[15];
    const float* proj_W  = (const float*)d_in[16];
    const float* proj_b  = (const float*)d_in[17];
    float* out = (float*)d_out;

    fused_front<<<FUSED_GRID, 128>>>(x, node_W, node_b, ei,
                                     lin1_b, bn_g, bn_b, bn_m, bn_v);
    scan_kernel<<<1, 1024>>>();
    edge_embed<<<(NE + 63) / 64, 128>>>(ei, ea, edge_W, edge_b);

    const int gemm_grid = (NN + 127) / 128;
    for (int li = 0; li < NL; li++) {
        // #4 (li==0) -> profiled: verify fp16-e prediction (~55us, DRAM ~60%)
        aggregate_kernel<<<(NN * 32 + 255) / 256, 256>>>();
        gemm1_kernel<<<gemm_grid, 256>>>(lin1_W + li * HH * HH, li);
        gemm2_kernel<<<gemm_grid, 256>>>(lin2_W + li * HH * HH, lin2_b + li * HH);
    }

    pool_kernel<<<(NN + 127) / 128, 128>>>(batch);
    proj_kernel<<<NG, 128>>>(proj_W, proj_b, out);
    cleanup_kernel<<<(NN + 255) / 256, 256>>>();
}

// round 14
// speedup vs baseline: 1.5956x; 1.2076x over previous
#include <cuda_runtime.h>
#include <cuda_fp16.h>
#include <cstdint>

#define NN 50000
#define NE 800000
#define NG 64
#define NF 11
#define EF 14
#define HH 128
#define PP 128
#define NL 3
#define BN_EPS 1e-5f

#define NE_BLOCKS 1563          // node-embed blocks (32 nodes each)
#define HIST_BLOCKS 1563        // hist blocks (512 edges each)
#define FUSED_GRID (NE_BLOCKS + HIST_BLOCKS + 3)

// ---------------- scratch (__device__ globals; device-code references only) --
// Invariant: g_cnt, g_pool, g_gcnt are ZERO on entry (re-zeroed by cleanup).
__device__ float  g_h[NN * HH];
__device__ float  g_z[NN * HH];
__device__ __half g_t[NN * HH];          // MLP intermediate, fp16 (ReLU output)
__device__ __half g_e[(size_t)NE * HH];  // edge embeddings, CSR order, fp16
__device__ int    g_cnt[NN];
__device__ int    g_row[NN + 1];
__device__ int    g_cur[NN];
__device__ int    g_src[NE];
__device__ float  g_scale[NL * HH];
__device__ float  g_shift[NL * HH];
__device__ float  g_pool[NG * HH];
__device__ float  g_gcnt[NG];

// ---------------- mma/ldmatrix helpers (sm80-style HMMA path) ---------------
__device__ __forceinline__ void ldsm_x4(uint32_t addr, uint32_t& r0, uint32_t& r1,
                                        uint32_t& r2, uint32_t& r3) {
    asm volatile("ldmatrix.sync.aligned.m8n8.x4.shared.b16 {%0,%1,%2,%3}, [%4];"
                 : "=r"(r0), "=r"(r1), "=r"(r2), "=r"(r3) : "r"(addr));
}
// NON-trans: W is stored [n][k] (= K x N col-major), fragment wants consecutive-k
__device__ __forceinline__ void ldsm_x2(uint32_t addr, uint32_t& r0, uint32_t& r1) {
    asm volatile("ldmatrix.sync.aligned.m8n8.x2.shared.b16 {%0,%1}, [%2];"
                 : "=r"(r0), "=r"(r1) : "r"(addr));
}
__device__ __forceinline__ void mma16816(float* d, uint32_t a0, uint32_t a1,
                                         uint32_t a2, uint32_t a3,
                                         uint32_t b0, uint32_t b1) {
    asm volatile(
        "mma.sync.aligned.m16n8k16.row.col.f32.f16.f16.f32 "
        "{%0,%1,%2,%3}, {%4,%5,%6,%7}, {%8,%9}, {%0,%1,%2,%3};"
        : "+f"(d[0]), "+f"(d[1]), "+f"(d[2]), "+f"(d[3])
        : "r"(a0), "r"(a1), "r"(a2), "r"(a3), "r"(b0), "r"(b1));
}
__device__ __forceinline__ uint32_t smem_u32(const void* p) {
    return (uint32_t)__cvta_generic_to_shared(p);
}

// ---------------- launch #1: node_embed + edge histogram + BN fold ----------
__global__ void __launch_bounds__(128) fused_front(const float* __restrict__ x,
                                                   const float* __restrict__ nW,
                                                   const float* __restrict__ nb,
                                                   const int* __restrict__ ei,
                                                   const float* __restrict__ lin1_b,
                                                   const float* __restrict__ gamma,
                                                   const float* __restrict__ beta,
                                                   const float* __restrict__ mean,
                                                   const float* __restrict__ var) {
    int b = blockIdx.x;
    int t = threadIdx.x;
    if (b < NE_BLOCKS) {
        __shared__ float xs[32 * NF];
        float w[NF];
#pragma unroll
        for (int k = 0; k < NF; k++) w[k] = nW[t * NF + k];
        float bias = nb[t];
        int base = b * 32;
        for (int i = t; i < 32 * NF; i += 128) {
            int node = base + i / NF;
            xs[i] = (node < NN) ? x[node * NF + i % NF] : 0.f;
        }
        __syncthreads();
        for (int j = 0; j < 32; j++) {
            int node = base + j;
            if (node >= NN) break;
            float acc = bias;
#pragma unroll
            for (int k = 0; k < NF; k++) acc = fmaf(xs[j * NF + k], w[k], acc);
            g_h[node * HH + t] = acc;
        }
    } else if (b < NE_BLOCKS + HIST_BLOCKS) {
        int base = (b - NE_BLOCKS) * 512;
#pragma unroll
        for (int r = 0; r < 4; r++) {
            int i = base + r * 128 + t;
            if (i < NE) atomicAdd(&g_cnt[ei[NE + i]], 1);
        }
    } else {
        int i = (b - NE_BLOCKS - HIST_BLOCKS) * 128 + t;
        if (i < NL * HH) {
            float sc = gamma[i] * rsqrtf(var[i] + BN_EPS);
            g_scale[i] = sc;
            g_shift[i] = (lin1_b[i] - mean[i]) * sc + beta[i];
        }
    }
}

// ---------------- launch #2: single-block scan ------------------------------
__global__ void __launch_bounds__(1024) scan_kernel() {
    __shared__ int partial[1024];
    const int CH = (NN + 1023) / 1024;   // 49
    int t = threadIdx.x;
    int beg = t * CH;
    int sum = 0;
    for (int i = 0; i < CH; i++) {
        int idx = beg + i;
        if (idx < NN) sum += g_cnt[idx];
    }
    partial[t] = sum;
    __syncthreads();
    for (int off = 1; off < 1024; off <<= 1) {
        int v = (t >= off) ? partial[t - off] : 0;
        __syncthreads();
        partial[t] += v;
        __syncthreads();
    }
    int run = (t > 0) ? partial[t - 1] : 0;
    for (int i = 0; i < CH; i++) {
        int idx = beg + i;
        if (idx < NN) {
            g_row[idx] = run;
            g_cur[idx] = run;
            run += g_cnt[idx];
        }
    }
    if (t == 1023) g_row[NN] = run;
}

// ---------------- launch #3: fused scatter + edge embedding (fp16 out) ------
__global__ void __launch_bounds__(128) edge_embed(const int* __restrict__ ei,
                                                  const float* __restrict__ ea,
                                                  const float* __restrict__ eW,
                                                  const float* __restrict__ eB) {
    __shared__ float es[64 * EF];
    __shared__ int pos[64];
    int t = threadIdx.x;
    int base = blockIdx.x * 64;

    if (t < 64) {
        int e = base + t;
        if (e < NE) {
            int d = ei[NE + e];
            int p = atomicAdd(&g_cur[d], 1);
            pos[t] = p;
            g_src[p] = ei[e];
        }
    }
    float w[EF];
#pragma unroll
    for (int k = 0; k < EF; k++) w[k] = eW[t * EF + k];
    float bias = eB[t];
    for (int i = t; i < 64 * EF; i += 128) {
        int e = base + i / EF;
        es[i] = (e < NE) ? ea[(size_t)e * EF + i % EF] : 0.f;
    }
    __syncthreads();
    int lim = NE - base; if (lim > 64) lim = 64;
    for (int j = 0; j < lim; j++) {
        float acc = bias;
#pragma unroll
        for (int k = 0; k < EF; k++) acc = fmaf(es[j * EF + k], w[k], acc);
        g_e[(size_t)pos[j] * HH + t] = __float2half_rn(acc);
    }
}

// ---------------- launch #4 (PROFILED control): streaming GINE aggregation --
__device__ __forceinline__ float4 half4_to_float4(uint2 v) {
    __half2 p0 = *reinterpret_cast<__half2*>(&v.x);
    __half2 p1 = *reinterpret_cast<__half2*>(&v.y);
    float2 f0 = __half22float2(p0);
    float2 f1 = __half22float2(p1);
    return make_float4(f0.x, f0.y, f1.x, f1.y);
}

__global__ void __launch_bounds__(256) aggregate_kernel() {
    int gid = blockIdx.x * blockDim.x + threadIdx.x;
    int node = gid >> 5;
    if (node >= NN) return;
    int lane = gid & 31;
    const float4* hp = (const float4*)g_h;
    const uint2* ep = (const uint2*)g_e;   // 8B = 4 halfs per lane
    float4 accA = make_float4(0.f, 0.f, 0.f, 0.f);
    float4 accB = make_float4(0.f, 0.f, 0.f, 0.f);
    int beg = g_row[node], end = g_row[node + 1];
    int i = beg;
    for (; i + 2 <= end; i += 2) {
        int s0 = __ldg(&g_src[i]);
        int s1 = __ldg(&g_src[i + 1]);
        float4 e0 = half4_to_float4(ep[(size_t)i * 32 + lane]);
        float4 e1 = half4_to_float4(ep[(size_t)(i + 1) * 32 + lane]);
        float4 h0 = hp[s0 * 32 + lane];
        float4 h1 = hp[s1 * 32 + lane];
        accA.x += fmaxf(h0.x + e0.x, 0.f);  accB.x += fmaxf(h1.x + e1.x, 0.f);
        accA.y += fmaxf(h0.y + e0.y, 0.f);  accB.y += fmaxf(h1.y + e1.y, 0.f);
        accA.z += fmaxf(h0.z + e0.z, 0.f);  accB.z += fmaxf(h1.z + e1.z, 0.f);
        accA.w += fmaxf(h0.w + e0.w, 0.f);  accB.w += fmaxf(h1.w + e1.w, 0.f);
    }
    if (i < end) {
        int s0 = __ldg(&g_src[i]);
        float4 e0 = half4_to_float4(ep[(size_t)i * 32 + lane]);
        float4 h0 = hp[s0 * 32 + lane];
        accA.x += fmaxf(h0.x + e0.x, 0.f);
        accA.y += fmaxf(h0.y + e0.y, 0.f);
        accA.z += fmaxf(h0.z + e0.z, 0.f);
        accA.w += fmaxf(h0.w + e0.w, 0.f);
    }
    float4 hv = hp[node * 32 + lane];
    accA.x += accB.x + hv.x;
    accA.y += accB.y + hv.y;
    accA.z += accB.z + hv.z;
    accA.w += accB.w + hv.w;
    ((float4*)g_z)[node * 32 + lane] = accA;
}

// ---------------- HMMA GEMM: 128x128 tile, K=128, fp16 in / fp32 acc --------
// smem: A [128][136] half + W [128][136] half (pad -> conflict-free ldmatrix)
#define LDA 136
#define GEMM_SMEM_BYTES (2 * 128 * LDA * 2)   // 69632

// stage fp32 source (rows guarded) as fp16 into padded smem tile
__device__ __forceinline__ void stage_f32(const float* __restrict__ src,
                                          __half* dst, int rowbase, int t,
                                          bool guard) {
    const float4* s4 = (const float4*)src;
    for (int idx = t; idx < 128 * 32; idx += 256) {
        int m = idx >> 5, q = idx & 31;
        int row = rowbase + m;
        float4 v = make_float4(0.f, 0.f, 0.f, 0.f);
        if (!guard || row < NN) v = s4[row * 32 + q];
        __half2 h0 = __floats2half2_rn(v.x, v.y);
        __half2 h1 = __floats2half2_rn(v.z, v.w);
        uint2 u;
        u.x = *reinterpret_cast<uint32_t*>(&h0);
        u.y = *reinterpret_cast<uint32_t*>(&h1);
        *(uint2*)&dst[m * LDA + 4 * q] = u;
    }
}

// warp-level mma mainloop: 8 warps as 4(m) x 2(n); warp tile 32x64
__device__ __forceinline__ void hmma_main(const __half* AS, const __half* WS,
                                          int t, float acc[2][8][4]) {
    int lane = t & 31, warp = t >> 5;
    int mbase = (warp & 3) * 32;
    int nbase = (warp >> 2) * 64;

    uint32_t a_addr[2], b_addr[8];
#pragma unroll
    for (int mt = 0; mt < 2; mt++) {
        int row = mbase + mt * 16 + (lane & 15);
        int col = (lane >> 4) * 8;
        a_addr[mt] = smem_u32(&AS[row * LDA + col]);
    }
#pragma unroll
    for (int nt = 0; nt < 8; nt++) {
        int n = nbase + nt * 8 + (lane & 7);
        int col = ((lane >> 3) & 1) * 8;
        b_addr[nt] = smem_u32(&WS[n * LDA + col]);
    }

#pragma unroll
    for (int ks = 0; ks < 8; ks++) {
        uint32_t koff = ks * 32;            // 16 halfs = 32 bytes
        uint32_t a[2][4], b[8][2];
#pragma unroll
        for (int mt = 0; mt < 2; mt++)
            ldsm_x4(a_addr[mt] + koff, a[mt][0], a[mt][1], a[mt][2], a[mt][3]);
#pragma unroll
        for (int nt = 0; nt < 8; nt++)
            ldsm_x2(b_addr[nt] + koff, b[nt][0], b[nt][1]);
#pragma unroll
        for (int mt = 0; mt < 2; mt++)
#pragma unroll
            for (int nt = 0; nt < 8; nt++)
                mma16816(acc[mt][nt], a[mt][0], a[mt][1], a[mt][2], a[mt][3],
                         b[nt][0], b[nt][1]);
    }
}

// pass 1: g_t(fp16) = relu(scale[li] * (g_z @ W1^T) + shift[li])
__global__ void __launch_bounds__(256) gemm1_kernel(const float* __restrict__ W1,
                                                    int li) {
    extern __shared__ __half smh[];
    __half* AS = smh;
    __half* WS = smh + 128 * LDA;
    int t = threadIdx.x;
    int rowbase = blockIdx.x * 128;

    stage_f32(g_z, AS, rowbase, t, true);
    stage_f32(W1, WS, 0, t, false);
    __syncthreads();

    float acc[2][8][4];
#pragma unroll
    for (int mt = 0; mt < 2; mt++)
#pragma unroll
        for (int nt = 0; nt < 8; nt++)
#pragma unroll
            for (int i = 0; i < 4; i++) acc[mt][nt][i] = 0.f;

    hmma_main(AS, WS, t, acc);

    int lane = t & 31, warp = t >> 5;
    int mbase = (warp & 3) * 32;
    int nbase = (warp >> 2) * 64;
    int gr = lane >> 2;          // 0..7
    int gc2 = (lane & 3) * 2;    // 0,2,4,6
#pragma unroll
    for (int nt = 0; nt < 8; nt++) {
        int col = nbase + nt * 8 + gc2;
        float sc0 = g_scale[li * HH + col],     sh0 = g_shift[li * HH + col];
        float sc1 = g_scale[li * HH + col + 1], sh1 = g_shift[li * HH + col + 1];
#pragma unroll
        for (int mt = 0; mt < 2; mt++) {
            int r0 = rowbase + mbase + mt * 16 + gr;
            if (r0 < NN) {
                float v0 = fmaxf(fmaf(acc[mt][nt][0], sc0, sh0), 0.f);
                float v1 = fmaxf(fmaf(acc[mt][nt][1], sc1, sh1), 0.f);
                *(__half2*)&g_t[r0 * HH + col] = __floats2half2_rn(v0, v1);
            }
            int r1 = r0 + 8;
            if (r1 < NN) {
                float v0 = fmaxf(fmaf(acc[mt][nt][2], sc0, sh0), 0.f);
                float v1 = fmaxf(fmaf(acc[mt][nt][3], sc1, sh1), 0.f);
                *(__half2*)&g_t[r1 * HH + col] = __floats2half2_rn(v0, v1);
            }
        }
    }
}

// pass 2: g_h = relu(g_t @ W2^T + b2) + g_h
__global__ void __launch_bounds__(256) gemm2_kernel(const float* __restrict__ W2,
                                                    const float* __restrict__ b2) {
    extern __shared__ __half smh[];
    __half* AS = smh;
    __half* WS = smh + 128 * LDA;
    int t = threadIdx.x;
    int rowbase = blockIdx.x * 128;

    // stage fp16 g_t directly (uint4 = 8 halfs)
    {
        const uint4* s4 = (const uint4*)g_t;
        for (int idx = t; idx < 128 * 16; idx += 256) {
            int m = idx >> 4, q = idx & 15;
            int row = rowbase + m;
            uint4 v = make_uint4(0u, 0u, 0u, 0u);
            if (row < NN) v = s4[row * 16 + q];
            *(uint4*)&AS[m * LDA + 8 * q] = v;
        }
    }
    stage_f32(W2, WS, 0, t, false);
    __syncthreads();

    float acc[2][8][4];
#pragma unroll
    for (int mt = 0; mt < 2; mt++)
#pragma unroll
        for (int nt = 0; nt < 8; nt++)
#pragma unroll
            for (int i = 0; i < 4; i++) acc[mt][nt][i] = 0.f;

    hmma_main(AS, WS, t, acc);

    int lane = t & 31, warp = t >> 5;
    int mbase = (warp & 3) * 32;
    int nbase = (warp >> 2) * 64;
    int gr = lane >> 2;
    int gc2 = (lane & 3) * 2;
#pragma unroll
    for (int nt = 0; nt < 8; nt++) {
        int col = nbase + nt * 8 + gc2;
        float b0 = b2[col], b1 = b2[col + 1];
#pragma unroll
        for (int mt = 0; mt < 2; mt++) {
            int r0 = rowbase + mbase + mt * 16 + gr;
            if (r0 < NN) {
                float2 h = *(float2*)&g_h[r0 * HH + col];
                h.x += fmaxf(acc[mt][nt][0] + b0, 0.f);
                h.y += fmaxf(acc[mt][nt][1] + b1, 0.f);
                *(float2*)&g_h[r0 * HH + col] = h;
            }
            int r1 = r0 + 8;
            if (r1 < NN) {
                float2 h = *(float2*)&g_h[r1 * HH + col];
                h.x += fmaxf(acc[mt][nt][2] + b0, 0.f);
                h.y += fmaxf(acc[mt][nt][3] + b1, 0.f);
                *(float2*)&g_h[r1 * HH + col] = h;
            }
        }
    }
}

// ---------------- pooling ----------------------------------------------------
__global__ void __launch_bounds__(128) pool_kernel(const int* __restrict__ batch) {
    int t = threadIdx.x;
    int base = blockIdx.x * 128;
    float acc = 0.f, runc = 0.f;
    int cur = -1;
    for (int j = 0; j < 128; j++) {
        int node = base + j;
        if (node >= NN) break;
        int g = batch[node];
        if (g != cur) {
            if (cur >= 0) {
                atomicAdd(&g_pool[cur * 128 + t], acc);
                if (t == 0) atomicAdd(&g_gcnt[cur], runc);
            }
            cur = g; acc = 0.f; runc = 0.f;
        }
        acc += g_h[node * 128 + t];
        runc += 1.f;
    }
    if (cur >= 0) {
        atomicAdd(&g_pool[cur * 128 + t], acc);
        if (t == 0) atomicAdd(&g_gcnt[cur], runc);
    }
}

// ---------------- final projection ------------------------------------------
__global__ void __launch_bounds__(128) proj_kernel(const float* __restrict__ pW,
                                                   const float* __restrict__ pb,
                                                   float* __restrict__ out) {
    __shared__ float pr[128];
    int g = blockIdx.x, t = threadIdx.x;
    float c = fmaxf(g_gcnt[g], 1.f);
    pr[t] = g_pool[g * 128 + t] / c;
    __syncthreads();
    float acc = pb[t];
#pragma unroll 4
    for (int h = 0; h < 128; h++) acc = fmaf(pr[h], pW[t * 128 + h], acc);
    out[g * 128 + t] = acc;
}

// ---------------- cleanup: restore zero-invariant for next call -------------
__global__ void __launch_bounds__(256) cleanup_kernel() {
    int i = blockIdx.x * blockDim.x + threadIdx.x;
    if (i < NN) g_cnt[i] = 0;
    if (i < NG * HH) g_pool[i] = 0.f;
    if (i < NG) g_gcnt[i] = 0.f;
}

// ---------------- launch ------------------------------------------------------
extern "C" void kernel_launch(void* const* d_in, const int* in_sizes, int n_in,
                              void* d_out, int out_size) {
    const float* x       = (const float*)d_in[0];
    const int*   ei      = (const int*)  d_in[1];
    const float* ea      = (const float*)d_in[2];
    const int*   batch   = (const int*)  d_in[3];
    const float* node_W  = (const float*)d_in[4];
    const float* node_b  = (const float*)d_in[5];
    const float* edge_W  = (const float*)d_in[6];
    const float* edge_b  = (const float*)d_in[7];
    const float* lin1_W  = (const float*)d_in[8];
    const float* lin1_b  = (const float*)d_in[9];
    const float* bn_g    = (const float*)d_in[10];
    const float* bn_b    = (const float*)d_in[11];
    const float* bn_m    = (const float*)d_in[12];
    const float* bn_v    = (const float*)d_in[13];
    const float* lin2_W  = (const float*)d_in[14];
    const float* lin2_b  = (const float*)d_in[15];
    const float* proj_W  = (const float*)d_in[16];
    const float* proj_b  = (const float*)d_in[17];
    float* out = (float*)d_out;

    static bool attr_done = false;
    if (!attr_done) {
        cudaFuncSetAttribute(gemm1_kernel,
                             cudaFuncAttributeMaxDynamicSharedMemorySize,
                             GEMM_SMEM_BYTES);
        cudaFuncSetAttribute(gemm2_kernel,
                             cudaFuncAttributeMaxDynamicSharedMemorySize,
                             GEMM_SMEM_BYTES);
        attr_done = true;
    }

    fused_front<<<FUSED_GRID, 128>>>(x, node_W, node_b, ei,
                                     lin1_b, bn_g, bn_b, bn_m, bn_v);
    scan_kernel<<<1, 1024>>>();
    edge_embed<<<(NE + 63) / 64, 128>>>(ei, ea, edge_W, edge_b);

    const int gemm_grid = (NN + 127) / 128;
    for (int li = 0; li < NL; li++) {
        // #4 (li==0) -> profiled control (~60us expected)
        aggregate_kernel<<<(NN * 32 + 255) / 256, 256>>>();
        gemm1_kernel<<<gemm_grid, 256, GEMM_SMEM_BYTES>>>(lin1_W + li * HH * HH, li);
        gemm2_kernel<<<gemm_grid, 256, GEMM_SMEM_BYTES>>>(lin2_W + li * HH * HH,
                                                          lin2_b + li * HH);
    }

    pool_kernel<<<(NN + 127) / 128, 128>>>(batch);
    proj_kernel<<<NG, 128>>>(proj_W, proj_b, out);
    cleanup_kernel<<<(NN + 255) / 256, 256>>>();
}

// round 15
// speedup vs baseline: 1.6690x; 1.0460x over previous
#include <cuda_runtime.h>
#include <cuda_fp16.h>
#include <cstdint>

#define NN 50000
#define NE 800000
#define NG 64
#define NF 11
#define EF 14
#define HH 128
#define PP 128
#define NL 3
#define BN_EPS 1e-5f

#define NE_BLOCKS 1563          // node-embed blocks (32 nodes each)
#define HIST_BLOCKS 1563        // hist blocks (512 edges each)
#define FUSED_GRID (NE_BLOCKS + HIST_BLOCKS + 3)

// ---------------- scratch (__device__ globals; device-code references only) --
// Invariant: g_cnt, g_pool, g_gcnt are ZERO on entry (re-zeroed by cleanup).
__device__ float  g_h[NN * HH];          // node features, fp32 (residual stream)
__device__ __half g_h16[NN * HH];        // fp16 mirror of g_h (aggregation gather)
__device__ float  g_z[NN * HH];          // h + agg
__device__ __half g_e[(size_t)NE * HH];  // edge embeddings, CSR order, fp16
__device__ int    g_cnt[NN];
__device__ int    g_row[NN + 1];
__device__ int    g_cur[NN];
__device__ int    g_src[NE];
__device__ float  g_scale[NL * HH];
__device__ float  g_shift[NL * HH];
__device__ float  g_pool[NG * HH];
__device__ float  g_gcnt[NG];

// ---------------- mma/ldmatrix helpers (sm80-style HMMA path) ---------------
__device__ __forceinline__ void ldsm_x4(uint32_t addr, uint32_t& r0, uint32_t& r1,
                                        uint32_t& r2, uint32_t& r3) {
    asm volatile("ldmatrix.sync.aligned.m8n8.x4.shared.b16 {%0,%1,%2,%3}, [%4];"
                 : "=r"(r0), "=r"(r1), "=r"(r2), "=r"(r3) : "r"(addr));
}
// NON-trans: W is stored [n][k] (= K x N col-major), fragment wants consecutive-k
__device__ __forceinline__ void ldsm_x2(uint32_t addr, uint32_t& r0, uint32_t& r1) {
    asm volatile("ldmatrix.sync.aligned.m8n8.x2.shared.b16 {%0,%1}, [%2];"
                 : "=r"(r0), "=r"(r1) : "r"(addr));
}
__device__ __forceinline__ void mma16816(float* d, uint32_t a0, uint32_t a1,
                                         uint32_t a2, uint32_t a3,
                                         uint32_t b0, uint32_t b1) {
    asm volatile(
        "mma.sync.aligned.m16n8k16.row.col.f32.f16.f16.f32 "
        "{%0,%1,%2,%3}, {%4,%5,%6,%7}, {%8,%9}, {%0,%1,%2,%3};"
        : "+f"(d[0]), "+f"(d[1]), "+f"(d[2]), "+f"(d[3])
        : "r"(a0), "r"(a1), "r"(a2), "r"(a3), "r"(b0), "r"(b1));
}
__device__ __forceinline__ uint32_t smem_u32(const void* p) {
    return (uint32_t)__cvta_generic_to_shared(p);
}

// ---------------- launch #1: node_embed + edge histogram + BN fold ----------
__global__ void __launch_bounds__(128) fused_front(const float* __restrict__ x,
                                                   const float* __restrict__ nW,
                                                   const float* __restrict__ nb,
                                                   const int* __restrict__ ei,
                                                   const float* __restrict__ lin1_b,
                                                   const float* __restrict__ gamma,
                                                   const float* __restrict__ beta,
                                                   const float* __restrict__ mean,
                                                   const float* __restrict__ var) {
    int b = blockIdx.x;
    int t = threadIdx.x;
    if (b < NE_BLOCKS) {
        __shared__ float xs[32 * NF];
        float w[NF];
#pragma unroll
        for (int k = 0; k < NF; k++) w[k] = nW[t * NF + k];
        float bias = nb[t];
        int base = b * 32;
        for (int i = t; i < 32 * NF; i += 128) {
            int node = base + i / NF;
            xs[i] = (node < NN) ? x[node * NF + i % NF] : 0.f;
        }
        __syncthreads();
        for (int j = 0; j < 32; j++) {
            int node = base + j;
            if (node >= NN) break;
            float acc = bias;
#pragma unroll
            for (int k = 0; k < NF; k++) acc = fmaf(xs[j * NF + k], w[k], acc);
            g_h[node * HH + t] = acc;
            g_h16[node * HH + t] = __float2half_rn(acc);
        }
    } else if (b < NE_BLOCKS + HIST_BLOCKS) {
        int base = (b - NE_BLOCKS) * 512;
#pragma unroll
        for (int r = 0; r < 4; r++) {
            int i = base + r * 128 + t;
            if (i < NE) atomicAdd(&g_cnt[ei[NE + i]], 1);
        }
    } else {
        int i = (b - NE_BLOCKS - HIST_BLOCKS) * 128 + t;
        if (i < NL * HH) {
            float sc = gamma[i] * rsqrtf(var[i] + BN_EPS);
            g_scale[i] = sc;
            g_shift[i] = (lin1_b[i] - mean[i]) * sc + beta[i];
        }
    }
}

// ---------------- launch #2: single-block scan ------------------------------
__global__ void __launch_bounds__(1024) scan_kernel() {
    __shared__ int partial[1024];
    const int CH = (NN + 1023) / 1024;   // 49
    int t = threadIdx.x;
    int beg = t * CH;
    int sum = 0;
    for (int i = 0; i < CH; i++) {
        int idx = beg + i;
        if (idx < NN) sum += g_cnt[idx];
    }
    partial[t] = sum;
    __syncthreads();
    for (int off = 1; off < 1024; off <<= 1) {
        int v = (t >= off) ? partial[t - off] : 0;
        __syncthreads();
        partial[t] += v;
        __syncthreads();
    }
    int run = (t > 0) ? partial[t - 1] : 0;
    for (int i = 0; i < CH; i++) {
        int idx = beg + i;
        if (idx < NN) {
            g_row[idx] = run;
            g_cur[idx] = run;
            run += g_cnt[idx];
        }
    }
    if (t == 1023) g_row[NN] = run;
}

// ---------------- launch #3: fused scatter + edge embedding (fp16 out) ------
__global__ void __launch_bounds__(128) edge_embed(const int* __restrict__ ei,
                                                  const float* __restrict__ ea,
                                                  const float* __restrict__ eW,
                                                  const float* __restrict__ eB) {
    __shared__ float es[64 * EF];
    __shared__ int pos[64];
    int t = threadIdx.x;
    int base = blockIdx.x * 64;

    if (t < 64) {
        int e = base + t;
        if (e < NE) {
            int d = ei[NE + e];
            int p = atomicAdd(&g_cur[d], 1);
            pos[t] = p;
            g_src[p] = ei[e];
        }
    }
    float w[EF];
#pragma unroll
    for (int k = 0; k < EF; k++) w[k] = eW[t * EF + k];
    float bias = eB[t];
    for (int i = t; i < 64 * EF; i += 128) {
        int e = base + i / EF;
        es[i] = (e < NE) ? ea[(size_t)e * EF + i % EF] : 0.f;
    }
    __syncthreads();
    int lim = NE - base; if (lim > 64) lim = 64;
    for (int j = 0; j < lim; j++) {
        float acc = bias;
#pragma unroll
        for (int k = 0; k < EF; k++) acc = fmaf(es[j * EF + k], w[k], acc);
        g_e[(size_t)pos[j] * HH + t] = __float2half_rn(acc);
    }
}

// ---------------- launch #4 (PROFILED): streaming GINE aggregation ----------
// z = h + sum relu(h16[src] + e); neighbors gathered fp16, self term fp32.
__device__ __forceinline__ float4 half4_to_float4(uint2 v) {
    __half2 p0 = *reinterpret_cast<__half2*>(&v.x);
    __half2 p1 = *reinterpret_cast<__half2*>(&v.y);
    float2 f0 = __half22float2(p0);
    float2 f1 = __half22float2(p1);
    return make_float4(f0.x, f0.y, f1.x, f1.y);
}

__global__ void __launch_bounds__(256) aggregate_kernel() {
    int gid = blockIdx.x * blockDim.x + threadIdx.x;
    int node = gid >> 5;
    if (node >= NN) return;
    int lane = gid & 31;
    const float4* hp = (const float4*)g_h;
    const uint2* hp16 = (const uint2*)g_h16;   // 4 halfs per lane
    const uint2* ep = (const uint2*)g_e;
    float4 accA = make_float4(0.f, 0.f, 0.f, 0.f);
    float4 accB = make_float4(0.f, 0.f, 0.f, 0.f);
    int beg = g_row[node], end = g_row[node + 1];
    int i = beg;
    for (; i + 2 <= end; i += 2) {
        int s0 = __ldg(&g_src[i]);
        int s1 = __ldg(&g_src[i + 1]);
        float4 e0 = half4_to_float4(ep[(size_t)i * 32 + lane]);
        float4 e1 = half4_to_float4(ep[(size_t)(i + 1) * 32 + lane]);
        float4 h0 = half4_to_float4(hp16[s0 * 32 + lane]);
        float4 h1 = half4_to_float4(hp16[s1 * 32 + lane]);
        accA.x += fmaxf(h0.x + e0.x, 0.f);  accB.x += fmaxf(h1.x + e1.x, 0.f);
        accA.y += fmaxf(h0.y + e0.y, 0.f);  accB.y += fmaxf(h1.y + e1.y, 0.f);
        accA.z += fmaxf(h0.z + e0.z, 0.f);  accB.z += fmaxf(h1.z + e1.z, 0.f);
        accA.w += fmaxf(h0.w + e0.w, 0.f);  accB.w += fmaxf(h1.w + e1.w, 0.f);
    }
    if (i < end) {
        int s0 = __ldg(&g_src[i]);
        float4 e0 = half4_to_float4(ep[(size_t)i * 32 + lane]);
        float4 h0 = half4_to_float4(hp16[s0 * 32 + lane]);
        accA.x += fmaxf(h0.x + e0.x, 0.f);
        accA.y += fmaxf(h0.y + e0.y, 0.f);
        accA.z += fmaxf(h0.z + e0.z, 0.f);
        accA.w += fmaxf(h0.w + e0.w, 0.f);
    }
    float4 hv = hp[node * 32 + lane];       // self term stays fp32
    accA.x += accB.x + hv.x;
    accA.y += accB.y + hv.y;
    accA.z += accB.z + hv.z;
    accA.w += accB.w + hv.w;
    ((float4*)g_z)[node * 32 + lane] = accA;
}

// ---------------- fused HMMA MLP: lin1+BN+relu+lin2+relu+residual -----------
// 128x128 tile, K=128, fp16 in / fp32 acc. Intermediate lives in AS smem.
#define LDA 136
#define GEMM_SMEM_BYTES (2 * 128 * LDA * 2)   // 69632

// stage fp32 source (rows guarded) as fp16 into padded smem tile
__device__ __forceinline__ void stage_f32(const float* __restrict__ src,
                                          __half* dst, int rowbase, int t,
                                          bool guard) {
    const float4* s4 = (const float4*)src;
    for (int idx = t; idx < 128 * 32; idx += 256) {
        int m = idx >> 5, q = idx & 31;
        int row = rowbase + m;
        float4 v = make_float4(0.f, 0.f, 0.f, 0.f);
        if (!guard || row < NN) v = s4[row * 32 + q];
        __half2 h0 = __floats2half2_rn(v.x, v.y);
        __half2 h1 = __floats2half2_rn(v.z, v.w);
        uint2 u;
        u.x = *reinterpret_cast<uint32_t*>(&h0);
        u.y = *reinterpret_cast<uint32_t*>(&h1);
        *(uint2*)&dst[m * LDA + 4 * q] = u;
    }
}

// warp-level mma mainloop: 8 warps as 4(m) x 2(n); warp tile 32x64
__device__ __forceinline__ void hmma_main(const __half* AS, const __half* WS,
                                          int t, float acc[2][8][4]) {
    int lane = t & 31, warp = t >> 5;
    int mbase = (warp & 3) * 32;
    int nbase = (warp >> 2) * 64;

    uint32_t a_addr[2], b_addr[8];
#pragma unroll
    for (int mt = 0; mt < 2; mt++) {
        int row = mbase + mt * 16 + (lane & 15);
        int col = (lane >> 4) * 8;
        a_addr[mt] = smem_u32(&AS[row * LDA + col]);
    }
#pragma unroll
    for (int nt = 0; nt < 8; nt++) {
        int n = nbase + nt * 8 + (lane & 7);
        int col = ((lane >> 3) & 1) * 8;
        b_addr[nt] = smem_u32(&WS[n * LDA + col]);
    }

#pragma unroll
    for (int ks = 0; ks < 8; ks++) {
        uint32_t koff = ks * 32;            // 16 halfs = 32 bytes
        uint32_t a[2][4], b[8][2];
#pragma unroll
        for (int mt = 0; mt < 2; mt++)
            ldsm_x4(a_addr[mt] + koff, a[mt][0], a[mt][1], a[mt][2], a[mt][3]);
#pragma unroll
        for (int nt = 0; nt < 8; nt++)
            ldsm_x2(b_addr[nt] + koff, b[nt][0], b[nt][1]);
#pragma unroll
        for (int mt = 0; mt < 2; mt++)
#pragma unroll
            for (int nt = 0; nt < 8; nt++)
                mma16816(acc[mt][nt], a[mt][0], a[mt][1], a[mt][2], a[mt][3],
                         b[nt][0], b[nt][1]);
    }
}

__global__ void __launch_bounds__(256) mlp_kernel(const float* __restrict__ W1,
                                                  const float* __restrict__ W2,
                                                  const float* __restrict__ b2,
                                                  int li) {
    extern __shared__ __half smh[];
    __half* AS = smh;
    __half* WS = smh + 128 * LDA;
    int t = threadIdx.x;
    int rowbase = blockIdx.x * 128;

    stage_f32(g_z, AS, rowbase, t, true);
    stage_f32(W1, WS, 0, t, false);
    __syncthreads();

    float acc[2][8][4];
#pragma unroll
    for (int mt = 0; mt < 2; mt++)
#pragma unroll
        for (int nt = 0; nt < 8; nt++)
#pragma unroll
            for (int i = 0; i < 4; i++) acc[mt][nt][i] = 0.f;

    hmma_main(AS, WS, t, acc);
    __syncthreads();   // all reads of AS/WS done

    // epilogue 1: BN(folded)+relu -> fp16 back into AS; stage W2 over WS
    int lane = t & 31, warp = t >> 5;
    int mbase = (warp & 3) * 32;
    int nbase = (warp >> 2) * 64;
    int gr = lane >> 2;          // 0..7
    int gc2 = (lane & 3) * 2;    // 0,2,4,6
#pragma unroll
    for (int nt = 0; nt < 8; nt++) {
        int col = nbase + nt * 8 + gc2;
        float sc0 = g_scale[li * HH + col],     sh0 = g_shift[li * HH + col];
        float sc1 = g_scale[li * HH + col + 1], sh1 = g_shift[li * HH + col + 1];
#pragma unroll
        for (int mt = 0; mt < 2; mt++) {
            int m0 = mbase + mt * 16 + gr;
            float v0 = fmaxf(fmaf(acc[mt][nt][0], sc0, sh0), 0.f);
            float v1 = fmaxf(fmaf(acc[mt][nt][1], sc1, sh1), 0.f);
            *(__half2*)&AS[m0 * LDA + col] = __floats2half2_rn(v0, v1);
            float v2 = fmaxf(fmaf(acc[mt][nt][2], sc0, sh0), 0.f);
            float v3 = fmaxf(fmaf(acc[mt][nt][3], sc1, sh1), 0.f);
            *(__half2*)&AS[(m0 + 8) * LDA + col] = __floats2half2_rn(v2, v3);
        }
    }
    stage_f32(W2, WS, 0, t, false);
    __syncthreads();

#pragma unroll
    for (int mt = 0; mt < 2; mt++)
#pragma unroll
        for (int nt = 0; nt < 8; nt++)
#pragma unroll
            for (int i = 0; i < 4; i++) acc[mt][nt][i] = 0.f;

    hmma_main(AS, WS, t, acc);

    // epilogue 2: relu + residual into g_h (fp32) and g_h16 mirror
#pragma unroll
    for (int nt = 0; nt < 8; nt++) {
        int col = nbase + nt * 8 + gc2;
        float b0 = b2[col], b1 = b2[col + 1];
#pragma unroll
        for (int mt = 0; mt < 2; mt++) {
            int r0 = rowbase + mbase + mt * 16 + gr;
            if (r0 < NN) {
                float2 h = *(float2*)&g_h[r0 * HH + col];
                h.x += fmaxf(acc[mt][nt][0] + b0, 0.f);
                h.y += fmaxf(acc[mt][nt][1] + b1, 0.f);
                *(float2*)&g_h[r0 * HH + col] = h;
                *(__half2*)&g_h16[r0 * HH + col] = __floats2half2_rn(h.x, h.y);
            }
            int r1 = r0 + 8;
            if (r1 < NN) {
                float2 h = *(float2*)&g_h[r1 * HH + col];
                h.x += fmaxf(acc[mt][nt][2] + b0, 0.f);
                h.y += fmaxf(acc[mt][nt][3] + b1, 0.f);
                *(float2*)&g_h[r1 * HH + col] = h;
                *(__half2*)&g_h16[r1 * HH + col] = __floats2half2_rn(h.x, h.y);
            }
        }
    }
}

// ---------------- pooling ----------------------------------------------------
__global__ void __launch_bounds__(128) pool_kernel(const int* __restrict__ batch) {
    int t = threadIdx.x;
    int base = blockIdx.x * 128;
    float acc = 0.f, runc = 0.f;
    int cur = -1;
    for (int j = 0; j < 128; j++) {
        int node = base + j;
        if (node >= NN) break;
        int g = batch[node];
        if (g != cur) {
            if (cur >= 0) {
                atomicAdd(&g_pool[cur * 128 + t], acc);
                if (t == 0) atomicAdd(&g_gcnt[cur], runc);
            }
            cur = g; acc = 0.f; runc = 0.f;
        }
        acc += g_h[node * 128 + t];
        runc += 1.f;
    }
    if (cur >= 0) {
        atomicAdd(&g_pool[cur * 128 + t], acc);
        if (t == 0) atomicAdd(&g_gcnt[cur], runc);
    }
}

// ---------------- final projection ------------------------------------------
__global__ void __launch_bounds__(128) proj_kernel(const float* __restrict__ pW,
                                                   const float* __restrict__ pb,
                                                   float* __restrict__ out) {
    __shared__ float pr[128];
    int g = blockIdx.x, t = threadIdx.x;
    float c = fmaxf(g_gcnt[g], 1.f);
    pr[t] = g_pool[g * 128 + t] / c;
    __syncthreads();
    float acc = pb[t];
#pragma unroll 4
    for (int h = 0; h < 128; h++) acc = fmaf(pr[h], pW[t * 128 + h], acc);
    out[g * 128 + t] = acc;
}

// ---------------- cleanup: restore zero-invariant for next call -------------
__global__ void __launch_bounds__(256) cleanup_kernel() {
    int i = blockIdx.x * blockDim.x + threadIdx.x;
    if (i < NN) g_cnt[i] = 0;
    if (i < NG * HH) g_pool[i] = 0.f;
    if (i < NG) g_gcnt[i] = 0.f;
}

// ---------------- launch ------------------------------------------------------
extern "C" void kernel_launch(void* const* d_in, const int* in_sizes, int n_in,
                              void* d_out, int out_size) {
    const float* x       = (const float*)d_in[0];
    const int*   ei      = (const int*)  d_in[1];
    const float* ea      = (const float*)d_in[2];
    const int*   batch   = (const int*)  d_in[3];
    const float* node_W  = (const float*)d_in[4];
    const float* node_b  = (const float*)d_in[5];
    const float* edge_W  = (const float*)d_in[6];
    const float* edge_b  = (const float*)d_in[7];
    const float* lin1_W  = (const float*)d_in[8];
    const float* lin1_b  = (const float*)d_in[9];
    const float* bn_g    = (const float*)d_in[10];
    const float* bn_b    = (const float*)d_in[11];
    const float* bn_m    = (const float*)d_in[12];
    const float* bn_v    = (const float*)d_in[13];
    const float* lin2_W  = (const float*)d_in[14];
    const float* lin2_b  = (const float*)d_in[15];
    const float* proj_W  = (const float*)d_in[16];
    const float* proj_b  = (const float*)d_in[17];
    float* out = (float*)d_out;

    static bool attr_done = false;
    if (!attr_done) {
        cudaFuncSetAttribute(mlp_kernel,
                             cudaFuncAttributeMaxDynamicSharedMemorySize,
                             GEMM_SMEM_BYTES);
        attr_done = true;
    }

    fused_front<<<FUSED_GRID, 128>>>(x, node_W, node_b, ei,
                                     lin1_b, bn_g, bn_b, bn_m, bn_v);
    scan_kernel<<<1, 1024>>>();
    edge_embed<<<(NE + 63) / 64, 128>>>(ei, ea, edge_W, edge_b);

    const int gemm_grid = (NN + 127) / 128;
    for (int li = 0; li < NL; li++) {
        // #4 (li==0) -> profiled: verify h16-gather prediction (~48-52us)
        aggregate_kernel<<<(NN * 32 + 255) / 256, 256>>>();
        mlp_kernel<<<gemm_grid, 256, GEMM_SMEM_BYTES>>>(
            lin1_W + li * HH * HH, lin2_W + li * HH * HH, lin2_b + li * HH, li);
    }

    pool_kernel<<<(NN + 127) / 128, 128>>>(batch);
    proj_kernel<<<NG, 128>>>(proj_W, proj_b, out);
    cleanup_kernel<<<(NN + 255) / 256, 256>>>();
}

// round 16
// speedup vs baseline: 1.7936x; 1.0746x over previous
#include <cuda_runtime.h>
#include <cuda_fp16.h>
#include <cstdint>

#define NN 50000
#define NE 800000
#define NG 64
#define NF 11
#define EF 14
#define HH 128
#define PP 128
#define NL 3
#define BN_EPS 1e-5f

#define NE_BLOCKS 1563          // node-embed blocks (32 nodes each)
#define HIST_BLOCKS 1563        // hist blocks (512 edges each)
#define FUSED_GRID (NE_BLOCKS + HIST_BLOCKS + 3)

// ---------------- scratch (__device__ globals; device-code references only) --
// Invariant: g_cnt, g_pool, g_gcnt are ZERO on entry (re-zeroed by cleanup).
__device__ float  g_h[NN * HH];          // node features, fp32 (residual stream)
__device__ __half g_h16[NN * HH];        // fp16 mirror of g_h (aggregation gather)
__device__ float  g_z[NN * HH];          // h + agg
__device__ __half g_e[(size_t)NE * HH];  // edge embeddings, CSR order, fp16
__device__ int    g_cnt[NN];
__device__ int    g_row[NN + 1];
__device__ int    g_cur[NN];
__device__ int    g_src[NE];
__device__ float  g_scale[NL * HH];
__device__ float  g_shift[NL * HH];
__device__ float  g_pool[NG * HH];
__device__ float  g_gcnt[NG];

// ---------------- mma/ldmatrix helpers (sm80-style HMMA path) ---------------
__device__ __forceinline__ void ldsm_x4(uint32_t addr, uint32_t& r0, uint32_t& r1,
                                        uint32_t& r2, uint32_t& r3) {
    asm volatile("ldmatrix.sync.aligned.m8n8.x4.shared.b16 {%0,%1,%2,%3}, [%4];"
                 : "=r"(r0), "=r"(r1), "=r"(r2), "=r"(r3) : "r"(addr));
}
// NON-trans: W is stored [n][k] (= K x N col-major), fragment wants consecutive-k
__device__ __forceinline__ void ldsm_x2(uint32_t addr, uint32_t& r0, uint32_t& r1) {
    asm volatile("ldmatrix.sync.aligned.m8n8.x2.shared.b16 {%0,%1}, [%2];"
                 : "=r"(r0), "=r"(r1) : "r"(addr));
}
__device__ __forceinline__ void mma16816(float* d, uint32_t a0, uint32_t a1,
                                         uint32_t a2, uint32_t a3,
                                         uint32_t b0, uint32_t b1) {
    asm volatile(
        "mma.sync.aligned.m16n8k16.row.col.f32.f16.f16.f32 "
        "{%0,%1,%2,%3}, {%4,%5,%6,%7}, {%8,%9}, {%0,%1,%2,%3};"
        : "+f"(d[0]), "+f"(d[1]), "+f"(d[2]), "+f"(d[3])
        : "r"(a0), "r"(a1), "r"(a2), "r"(a3), "r"(b0), "r"(b1));
}
__device__ __forceinline__ uint32_t smem_u32(const void* p) {
    return (uint32_t)__cvta_generic_to_shared(p);
}

// ---------------- launch #1: node_embed + edge histogram + BN fold ----------
__global__ void __launch_bounds__(128) fused_front(const float* __restrict__ x,
                                                   const float* __restrict__ nW,
                                                   const float* __restrict__ nb,
                                                   const int* __restrict__ ei,
                                                   const float* __restrict__ lin1_b,
                                                   const float* __restrict__ gamma,
                                                   const float* __restrict__ beta,
                                                   const float* __restrict__ mean,
                                                   const float* __restrict__ var) {
    int b = blockIdx.x;
    int t = threadIdx.x;
    if (b < NE_BLOCKS) {
        __shared__ float xs[32 * NF];
        float w[NF];
#pragma unroll
        for (int k = 0; k < NF; k++) w[k] = nW[t * NF + k];
        float bias = nb[t];
        int base = b * 32;
        for (int i = t; i < 32 * NF; i += 128) {
            int node = base + i / NF;
            xs[i] = (node < NN) ? x[node * NF + i % NF] : 0.f;
        }
        __syncthreads();
        for (int j = 0; j < 32; j++) {
            int node = base + j;
            if (node >= NN) break;
            float acc = bias;
#pragma unroll
            for (int k = 0; k < NF; k++) acc = fmaf(xs[j * NF + k], w[k], acc);
            g_h[node * HH + t] = acc;
            g_h16[node * HH + t] = __float2half_rn(acc);
        }
    } else if (b < NE_BLOCKS + HIST_BLOCKS) {
        int base = (b - NE_BLOCKS) * 512;
#pragma unroll
        for (int r = 0; r < 4; r++) {
            int i = base + r * 128 + t;
            if (i < NE) atomicAdd(&g_cnt[ei[NE + i]], 1);
        }
    } else {
        int i = (b - NE_BLOCKS - HIST_BLOCKS) * 128 + t;
        if (i < NL * HH) {
            float sc = gamma[i] * rsqrtf(var[i] + BN_EPS);
            g_scale[i] = sc;
            g_shift[i] = (lin1_b[i] - mean[i]) * sc + beta[i];
        }
    }
}

// ---------------- launch #2: single-block scan ------------------------------
__global__ void __launch_bounds__(1024) scan_kernel() {
    __shared__ int partial[1024];
    const int CH = (NN + 1023) / 1024;   // 49
    int t = threadIdx.x;
    int beg = t * CH;
    int sum = 0;
    for (int i = 0; i < CH; i++) {
        int idx = beg + i;
        if (idx < NN) sum += g_cnt[idx];
    }
    partial[t] = sum;
    __syncthreads();
    for (int off = 1; off < 1024; off <<= 1) {
        int v = (t >= off) ? partial[t - off] : 0;
        __syncthreads();
        partial[t] += v;
        __syncthreads();
    }
    int run = (t > 0) ? partial[t - 1] : 0;
    for (int i = 0; i < CH; i++) {
        int idx = beg + i;
        if (idx < NN) {
            g_row[idx] = run;
            g_cur[idx] = run;
            run += g_cnt[idx];
        }
    }
    if (t == 1023) g_row[NN] = run;
}

// ---------------- launch #3: fused scatter + edge embedding (HFMA2) ---------
// 64 edges/block (NE % 64 == 0), processed as 32 packed pairs.
__global__ void __launch_bounds__(128) edge_embed(const int* __restrict__ ei,
                                                  const float* __restrict__ ea,
                                                  const float* __restrict__ eW,
                                                  const float* __restrict__ eB) {
    __shared__ __half2 es2[32 * EF];   // [pair][k] = (e0_k, e1_k)
    __shared__ int pos[64];
    int t = threadIdx.x;
    int base = blockIdx.x * 64;

    if (t < 64) {
        int e = base + t;
        int d = ei[NE + e];
        int p = atomicAdd(&g_cur[d], 1);
        pos[t] = p;
        g_src[p] = ei[e];
    }
    __half2 w2[EF];
#pragma unroll
    for (int k = 0; k < EF; k++) w2[k] = __float2half2_rn(eW[t * EF + k]);
    __half2 bias2 = __float2half2_rn(eB[t]);

    for (int i = t; i < 32 * EF; i += 128) {
        int pr = i / EF, k = i % EF;
        size_t e0 = (size_t)(base + 2 * pr) * EF + k;
        es2[i] = __floats2half2_rn(ea[e0], ea[e0 + EF]);
    }
    __syncthreads();

#pragma unroll 4
    for (int pr = 0; pr < 32; pr++) {
        __half2 acc = bias2;
#pragma unroll
        for (int k = 0; k < EF; k++) acc = __hfma2(w2[k], es2[pr * EF + k], acc);
        g_e[(size_t)pos[2 * pr] * HH + t]     = __low2half(acc);
        g_e[(size_t)pos[2 * pr + 1] * HH + t] = __high2half(acc);
    }
}

// ---------------- launch #4 (PROFILED): streaming GINE aggregation ----------
// z = h + sum relu(h16[src] + e); neighbors gathered fp16, self term fp32.
__device__ __forceinline__ float4 half4_to_float4(uint2 v) {
    __half2 p0 = *reinterpret_cast<__half2*>(&v.x);
    __half2 p1 = *reinterpret_cast<__half2*>(&v.y);
    float2 f0 = __half22float2(p0);
    float2 f1 = __half22float2(p1);
    return make_float4(f0.x, f0.y, f1.x, f1.y);
}

__global__ void __launch_bounds__(256) aggregate_kernel() {
    int gid = blockIdx.x * blockDim.x + threadIdx.x;
    int node = gid >> 5;
    if (node >= NN) return;
    int lane = gid & 31;
    const float4* hp = (const float4*)g_h;
    const uint2* hp16 = (const uint2*)g_h16;   // 4 halfs per lane
    const uint2* ep = (const uint2*)g_e;
    float4 accA = make_float4(0.f, 0.f, 0.f, 0.f);
    float4 accB = make_float4(0.f, 0.f, 0.f, 0.f);
    int beg = g_row[node], end = g_row[node + 1];
    int i = beg;
    for (; i + 2 <= end; i += 2) {
        int s0 = __ldg(&g_src[i]);
        int s1 = __ldg(&g_src[i + 1]);
        float4 e0 = half4_to_float4(ep[(size_t)i * 32 + lane]);
        float4 e1 = half4_to_float4(ep[(size_t)(i + 1) * 32 + lane]);
        float4 h0 = half4_to_float4(hp16[s0 * 32 + lane]);
        float4 h1 = half4_to_float4(hp16[s1 * 32 + lane]);
        accA.x += fmaxf(h0.x + e0.x, 0.f);  accB.x += fmaxf(h1.x + e1.x, 0.f);
        accA.y += fmaxf(h0.y + e0.y, 0.f);  accB.y += fmaxf(h1.y + e1.y, 0.f);
        accA.z += fmaxf(h0.z + e0.z, 0.f);  accB.z += fmaxf(h1.z + e1.z, 0.f);
        accA.w += fmaxf(h0.w + e0.w, 0.f);  accB.w += fmaxf(h1.w + e1.w, 0.f);
    }
    if (i < end) {
        int s0 = __ldg(&g_src[i]);
        float4 e0 = half4_to_float4(ep[(size_t)i * 32 + lane]);
        float4 h0 = half4_to_float4(hp16[s0 * 32 + lane]);
        accA.x += fmaxf(h0.x + e0.x, 0.f);
        accA.y += fmaxf(h0.y + e0.y, 0.f);
        accA.z += fmaxf(h0.z + e0.z, 0.f);
        accA.w += fmaxf(h0.w + e0.w, 0.f);
    }
    float4 hv = hp[node * 32 + lane];       // self term stays fp32
    accA.x += accB.x + hv.x;
    accA.y += accB.y + hv.y;
    accA.z += accB.z + hv.z;
    accA.w += accB.w + hv.w;
    ((float4*)g_z)[node * 32 + lane] = accA;
}

// ---------------- fused HMMA MLP: lin1+BN+relu+lin2+relu+residual -----------
// 128x128 tile, K=128, fp16 in / fp32 acc. Intermediate lives in AS smem.
// W1 and W2 both staged before mainloop1 (WS, WS2) to hide the W2 load.
#define LDA 136
#define GEMM_SMEM_BYTES (3 * 128 * LDA * 2)   // 104448

// stage fp32 source (rows guarded) as fp16 into padded smem tile
__device__ __forceinline__ void stage_f32(const float* __restrict__ src,
                                          __half* dst, int rowbase, int t,
                                          bool guard) {
    const float4* s4 = (const float4*)src;
    for (int idx = t; idx < 128 * 32; idx += 256) {
        int m = idx >> 5, q = idx & 31;
        int row = rowbase + m;
        float4 v = make_float4(0.f, 0.f, 0.f, 0.f);
        if (!guard || row < NN) v = s4[row * 32 + q];
        __half2 h0 = __floats2half2_rn(v.x, v.y);
        __half2 h1 = __floats2half2_rn(v.z, v.w);
        uint2 u;
        u.x = *reinterpret_cast<uint32_t*>(&h0);
        u.y = *reinterpret_cast<uint32_t*>(&h1);
        *(uint2*)&dst[m * LDA + 4 * q] = u;
    }
}

// warp-level mma mainloop: 8 warps as 4(m) x 2(n); warp tile 32x64
__device__ __forceinline__ void hmma_main(const __half* AS, const __half* WS,
                                          int t, float acc[2][8][4]) {
    int lane = t & 31, warp = t >> 5;
    int mbase = (warp & 3) * 32;
    int nbase = (warp >> 2) * 64;

    uint32_t a_addr[2], b_addr[8];
#pragma unroll
    for (int mt = 0; mt < 2; mt++) {
        int row = mbase + mt * 16 + (lane & 15);
        int col = (lane >> 4) * 8;
        a_addr[mt] = smem_u32(&AS[row * LDA + col]);
    }
#pragma unroll
    for (int nt = 0; nt < 8; nt++) {
        int n = nbase + nt * 8 + (lane & 7);
        int col = ((lane >> 3) & 1) * 8;
        b_addr[nt] = smem_u32(&WS[n * LDA + col]);
    }

#pragma unroll
    for (int ks = 0; ks < 8; ks++) {
        uint32_t koff = ks * 32;            // 16 halfs = 32 bytes
        uint32_t a[2][4], b[8][2];
#pragma unroll
        for (int mt = 0; mt < 2; mt++)
            ldsm_x4(a_addr[mt] + koff, a[mt][0], a[mt][1], a[mt][2], a[mt][3]);
#pragma unroll
        for (int nt = 0; nt < 8; nt++)
            ldsm_x2(b_addr[nt] + koff, b[nt][0], b[nt][1]);
#pragma unroll
        for (int mt = 0; mt < 2; mt++)
#pragma unroll
            for (int nt = 0; nt < 8; nt++)
                mma16816(acc[mt][nt], a[mt][0], a[mt][1], a[mt][2], a[mt][3],
                         b[nt][0], b[nt][1]);
    }
}

__global__ void __launch_bounds__(256) mlp_kernel(const float* __restrict__ W1,
                                                  const float* __restrict__ W2,
                                                  const float* __restrict__ b2,
                                                  int li) {
    extern __shared__ __half smh[];
    __half* AS  = smh;
    __half* WS  = smh + 128 * LDA;
    __half* WS2 = smh + 2 * 128 * LDA;
    int t = threadIdx.x;
    int rowbase = blockIdx.x * 128;

    stage_f32(g_z, AS, rowbase, t, true);
    stage_f32(W1, WS, 0, t, false);
    stage_f32(W2, WS2, 0, t, false);   // staged early; used by mainloop2
    __syncthreads();

    float acc[2][8][4];
#pragma unroll
    for (int mt = 0; mt < 2; mt++)
#pragma unroll
        for (int nt = 0; nt < 8; nt++)
#pragma unroll
            for (int i = 0; i < 4; i++) acc[mt][nt][i] = 0.f;

    hmma_main(AS, WS, t, acc);
    __syncthreads();   // all reads of AS done before rewrite

    // epilogue 1: BN(folded)+relu -> fp16 back into AS
    int lane = t & 31, warp = t >> 5;
    int mbase = (warp & 3) * 32;
    int nbase = (warp >> 2) * 64;
    int gr = lane >> 2;          // 0..7
    int gc2 = (lane & 3) * 2;    // 0,2,4,6
#pragma unroll
    for (int nt = 0; nt < 8; nt++) {
        int col = nbase + nt * 8 + gc2;
        float sc0 = g_scale[li * HH + col],     sh0 = g_shift[li * HH + col];
        float sc1 = g_scale[li * HH + col + 1], sh1 = g_shift[li * HH + col + 1];
#pragma unroll
        for (int mt = 0; mt < 2; mt++) {
            int m0 = mbase + mt * 16 + gr;
            float v0 = fmaxf(fmaf(acc[mt][nt][0], sc0, sh0), 0.f);
            float v1 = fmaxf(fmaf(acc[mt][nt][1], sc1, sh1), 0.f);
            *(__half2*)&AS[m0 * LDA + col] = __floats2half2_rn(v0, v1);
            float v2 = fmaxf(fmaf(acc[mt][nt][2], sc0, sh0), 0.f);
            float v3 = fmaxf(fmaf(acc[mt][nt][3], sc1, sh1), 0.f);
            *(__half2*)&AS[(m0 + 8) * LDA + col] = __floats2half2_rn(v2, v3);
        }
    }
    __syncthreads();

#pragma unroll
    for (int mt = 0; mt < 2; mt++)
#pragma unroll
        for (int nt = 0; nt < 8; nt++)
#pragma unroll
            for (int i = 0; i < 4; i++) acc[mt][nt][i] = 0.f;

    hmma_main(AS, WS2, t, acc);

    // epilogue 2: relu + residual into g_h (fp32) and g_h16 mirror
#pragma unroll
    for (int nt = 0; nt < 8; nt++) {
        int col = nbase + nt * 8 + gc2;
        float b0 = b2[col], b1 = b2[col + 1];
#pragma unroll
        for (int mt = 0; mt < 2; mt++) {
            int r0 = rowbase + mbase + mt * 16 + gr;
            if (r0 < NN) {
                float2 h = *(float2*)&g_h[r0 * HH + col];
                h.x += fmaxf(acc[mt][nt][0] + b0, 0.f);
                h.y += fmaxf(acc[mt][nt][1] + b1, 0.f);
                *(float2*)&g_h[r0 * HH + col] = h;
                *(__half2*)&g_h16[r0 * HH + col] = __floats2half2_rn(h.x, h.y);
            }
            int r1 = r0 + 8;
            if (r1 < NN) {
                float2 h = *(float2*)&g_h[r1 * HH + col];
                h.x += fmaxf(acc[mt][nt][2] + b0, 0.f);
                h.y += fmaxf(acc[mt][nt][3] + b1, 0.f);
                *(float2*)&g_h[r1 * HH + col] = h;
                *(__half2*)&g_h16[r1 * HH + col] = __floats2half2_rn(h.x, h.y);
            }
        }
    }
}

// ---------------- pooling ----------------------------------------------------
__global__ void __launch_bounds__(128) pool_kernel(const int* __restrict__ batch) {
    int t = threadIdx.x;
    int base = blockIdx.x * 128;
    float acc = 0.f, runc = 0.f;
    int cur = -1;
    for (int j = 0; j < 128; j++) {
        int node = base + j;
        if (node >= NN) break;
        int g = batch[node];
        if (g != cur) {
            if (cur >= 0) {
                atomicAdd(&g_pool[cur * 128 + t], acc);
                if (t == 0) atomicAdd(&g_gcnt[cur], runc);
            }
            cur = g; acc = 0.f; runc = 0.f;
        }
        acc += g_h[node * 128 + t];
        runc += 1.f;
    }
    if (cur >= 0) {
        atomicAdd(&g_pool[cur * 128 + t], acc);
        if (t == 0) atomicAdd(&g_gcnt[cur], runc);
    }
}

// ---------------- final projection ------------------------------------------
__global__ void __launch_bounds__(128) proj_kernel(const float* __restrict__ pW,
                                                   const float* __restrict__ pb,
                                                   float* __restrict__ out) {
    __shared__ float pr[128];
    int g = blockIdx.x, t = threadIdx.x;
    float c = fmaxf(g_gcnt[g], 1.f);
    pr[t] = g_pool[g * 128 + t] / c;
    __syncthreads();
    float acc = pb[t];
#pragma unroll 4
    for (int h = 0; h < 128; h++) acc = fmaf(pr[h], pW[t * 128 + h], acc);
    out[g * 128 + t] = acc;
}

// ---------------- cleanup: restore zero-invariant for next call -------------
__global__ void __launch_bounds__(256) cleanup_kernel() {
    int i = blockIdx.x * blockDim.x + threadIdx.x;
    if (i < NN) g_cnt[i] = 0;
    if (i < NG * HH) g_pool[i] = 0.f;
    if (i < NG) g_gcnt[i] = 0.f;
}

// ---------------- launch ------------------------------------------------------
extern "C" void kernel_launch(void* const* d_in, const int* in_sizes, int n_in,
                              void* d_out, int out_size) {
    const float* x       = (const float*)d_in[0];
    const int*   ei      = (const int*)  d_in[1];
    const float* ea      = (const float*)d_in[2];
    const int*   batch   = (const int*)  d_in[3];
    const float* node_W  = (const float*)d_in[4];
    const float* node_b  = (const float*)d_in[5];
    const float* edge_W  = (const float*)d_in[6];
    const float* edge_b  = (const float*)d_in[7];
    const float* lin1_W  = (const float*)d_in[8];
    const float* lin1_b  = (const float*)d_in[9];
    const float* bn_g    = (const float*)d_in[10];
    const float* bn_b    = (const float*)d_in[11];
    const float* bn_m    = (const float*)d_in[12];
    const float* bn_v    = (const float*)d_in[13];
    const float* lin2_W  = (const float*)d_in[14];
    const float* lin2_b  = (const float*)d_in[15];
    const float* proj_W  = (const float*)d_in[16];
    const float* proj_b  = (const float*)d_in[17];
    float* out = (float*)d_out;

    static bool attr_done = false;
    if (!attr_done) {
        cudaFuncSetAttribute(mlp_kernel,
                             cudaFuncAttributeMaxDynamicSharedMemorySize,
                             GEMM_SMEM_BYTES);
        attr_done = true;
    }

    fused_front<<<FUSED_GRID, 128>>>(x, node_W, node_b, ei,
                                     lin1_b, bn_g, bn_b, bn_m, bn_v);
    scan_kernel<<<1, 1024>>>();
    edge_embed<<<NE / 64, 128>>>(ei, ea, edge_W, edge_b);

    const int gemm_grid = (NN + 127) / 128;
    for (int li = 0; li < NL; li++) {
        // #4 (li==0) -> profiled control (~58us expected)
        aggregate_kernel<<<(NN * 32 + 255) / 256, 256>>>();
        mlp_kernel<<<gemm_grid, 256, GEMM_SMEM_BYTES>>>(
            lin1_W + li * HH * HH, lin2_W + li * HH * HH, lin2_b + li * HH, li);
    }

    pool_kernel<<<(NN + 127) / 128, 128>>>(batch);
    proj_kernel<<<NG, 128>>>(proj_W, proj_b, out);
    cleanup_kernel<<<(NN + 255) / 256, 256>>>();
}

// round 17
// speedup vs baseline: 1.7996x; 1.0033x over previous
#include <cuda_runtime.h>
#include <cuda_fp16.h>
#include <cstdint>

#define NN 50000
#define NE 800000
#define NG 64
#define NF 11
#define EF 14
#define HH 128
#define PP 128
#define NL 3
#define BN_EPS 1e-5f

#define NE_BLOCKS 1563          // node-embed blocks (32 nodes each)
#define HIST_BLOCKS 1563        // hist blocks (512 edges each)
#define WC_BLOCKS 192           // weight-convert blocks (512 floats each)
#define FUSED_GRID (NE_BLOCKS + HIST_BLOCKS + 3 + WC_BLOCKS)

// ---------------- scratch (__device__ globals; device-code references only) --
// Invariant: g_cnt, g_pool, g_gcnt are ZERO on entry (re-zeroed by cleanup).
__device__ float  g_h[NN * HH];          // node features, fp32 (residual stream)
__device__ __half g_h16[NN * HH];        // fp16 mirror of g_h (aggregation gather)
__device__ __half g_z16[NN * HH];        // h + agg, fp16 (GEMM input domain)
__device__ __half g_e[(size_t)NE * HH];  // edge embeddings, CSR order, fp16
__device__ __half g_w16[NL * 2 * HH * HH]; // fp16 weights: [li][W1,W2]
__device__ int    g_cnt[NN];
__device__ int    g_row[NN + 1];
__device__ int    g_cur[NN];
__device__ int    g_src[NE];
__device__ float  g_scale[NL * HH];
__device__ float  g_shift[NL * HH];
__device__ float  g_pool[NG * HH];
__device__ float  g_gcnt[NG];

// ---------------- mma/ldmatrix helpers (sm80-style HMMA path) ---------------
__device__ __forceinline__ void ldsm_x4(uint32_t addr, uint32_t& r0, uint32_t& r1,
                                        uint32_t& r2, uint32_t& r3) {
    asm volatile("ldmatrix.sync.aligned.m8n8.x4.shared.b16 {%0,%1,%2,%3}, [%4];"
                 : "=r"(r0), "=r"(r1), "=r"(r2), "=r"(r3) : "r"(addr));
}
// NON-trans: W is stored [n][k] (= K x N col-major), fragment wants consecutive-k
__device__ __forceinline__ void ldsm_x2(uint32_t addr, uint32_t& r0, uint32_t& r1) {
    asm volatile("ldmatrix.sync.aligned.m8n8.x2.shared.b16 {%0,%1}, [%2];"
                 : "=r"(r0), "=r"(r1) : "r"(addr));
}
__device__ __forceinline__ void mma16816(float* d, uint32_t a0, uint32_t a1,
                                         uint32_t a2, uint32_t a3,
                                         uint32_t b0, uint32_t b1) {
    asm volatile(
        "mma.sync.aligned.m16n8k16.row.col.f32.f16.f16.f32 "
        "{%0,%1,%2,%3}, {%4,%5,%6,%7}, {%8,%9}, {%0,%1,%2,%3};"
        : "+f"(d[0]), "+f"(d[1]), "+f"(d[2]), "+f"(d[3])
        : "r"(a0), "r"(a1), "r"(a2), "r"(a3), "r"(b0), "r"(b1));
}
__device__ __forceinline__ uint32_t smem_u32(const void* p) {
    return (uint32_t)__cvta_generic_to_shared(p);
}

// ---------------- launch #1: node_embed + hist + BN fold + weight cvt -------
__global__ void __launch_bounds__(128) fused_front(const float* __restrict__ x,
                                                   const float* __restrict__ nW,
                                                   const float* __restrict__ nb,
                                                   const int* __restrict__ ei,
                                                   const float* __restrict__ lin1_b,
                                                   const float* __restrict__ gamma,
                                                   const float* __restrict__ beta,
                                                   const float* __restrict__ mean,
                                                   const float* __restrict__ var,
                                                   const float* __restrict__ lin1_W,
                                                   const float* __restrict__ lin2_W) {
    int b = blockIdx.x;
    int t = threadIdx.x;
    if (b < NE_BLOCKS) {
        __shared__ float xs[32 * NF];
        float w[NF];
#pragma unroll
        for (int k = 0; k < NF; k++) w[k] = nW[t * NF + k];
        float bias = nb[t];
        int base = b * 32;
        for (int i = t; i < 32 * NF; i += 128) {
            int node = base + i / NF;
            xs[i] = (node < NN) ? x[node * NF + i % NF] : 0.f;
        }
        __syncthreads();
        for (int j = 0; j < 32; j++) {
            int node = base + j;
            if (node >= NN) break;
            float acc = bias;
#pragma unroll
            for (int k = 0; k < NF; k++) acc = fmaf(xs[j * NF + k], w[k], acc);
            g_h[node * HH + t] = acc;
            g_h16[node * HH + t] = __float2half_rn(acc);
        }
    } else if (b < NE_BLOCKS + HIST_BLOCKS) {
        int base = (b - NE_BLOCKS) * 512;
#pragma unroll
        for (int r = 0; r < 4; r++) {
            int i = base + r * 128 + t;
            if (i < NE) atomicAdd(&g_cnt[ei[NE + i]], 1);
        }
    } else if (b < NE_BLOCKS + HIST_BLOCKS + 3) {
        int i = (b - NE_BLOCKS - HIST_BLOCKS) * 128 + t;
        if (i < NL * HH) {
            float sc = gamma[i] * rsqrtf(var[i] + BN_EPS);
            g_scale[i] = sc;
            g_shift[i] = (lin1_b[i] - mean[i]) * sc + beta[i];
        }
    } else {
        // weight conversion: blocks [0,96) -> W1, [96,192) -> W2
        int wb = b - NE_BLOCKS - HIST_BLOCKS - 3;
        bool isW2 = (wb >= 96);
        int s = (isW2 ? wb - 96 : wb) * 512 + t * 4;   // float idx within source
        const float* src = isW2 ? lin2_W : lin1_W;
        int li = s / (HH * HH), rem = s % (HH * HH);
        float4 v = *(const float4*)&src[s];
        __half2 h0 = __floats2half2_rn(v.x, v.y);
        __half2 h1 = __floats2half2_rn(v.z, v.w);
        uint2 u;
        u.x = *reinterpret_cast<uint32_t*>(&h0);
        u.y = *reinterpret_cast<uint32_t*>(&h1);
        int dst = (li * 2 + (isW2 ? 1 : 0)) * HH * HH + rem;
        *(uint2*)&g_w16[dst] = u;
    }
}

// ---------------- launch #2: single-block scan ------------------------------
__global__ void __launch_bounds__(1024) scan_kernel() {
    __shared__ int partial[1024];
    const int CH = (NN + 1023) / 1024;   // 49
    int t = threadIdx.x;
    int beg = t * CH;
    int sum = 0;
    for (int i = 0; i < CH; i++) {
        int idx = beg + i;
        if (idx < NN) sum += g_cnt[idx];
    }
    partial[t] = sum;
    __syncthreads();
    for (int off = 1; off < 1024; off <<= 1) {
        int v = (t >= off) ? partial[t - off] : 0;
        __syncthreads();
        partial[t] += v;
        __syncthreads();
    }
    int run = (t > 0) ? partial[t - 1] : 0;
    for (int i = 0; i < CH; i++) {
        int idx = beg + i;
        if (idx < NN) {
            g_row[idx] = run;
            g_cur[idx] = run;
            run += g_cnt[idx];
        }
    }
    if (t == 1023) g_row[NN] = run;
}

// ---------------- launch #3: fused scatter + edge embedding (HFMA2) ---------
// 64 edges/block (NE % 64 == 0), processed as 32 packed pairs.
__global__ void __launch_bounds__(128) edge_embed(const int* __restrict__ ei,
                                                  const float* __restrict__ ea,
                                                  const float* __restrict__ eW,
                                                  const float* __restrict__ eB) {
    __shared__ __half2 es2[32 * EF];   // [pair][k] = (e0_k, e1_k)
    __shared__ int pos[64];
    int t = threadIdx.x;
    int base = blockIdx.x * 64;

    if (t < 64) {
        int e = base + t;
        int d = ei[NE + e];
        int p = atomicAdd(&g_cur[d], 1);
        pos[t] = p;
        g_src[p] = ei[e];
    }
    __half2 w2[EF];
#pragma unroll
    for (int k = 0; k < EF; k++) w2[k] = __float2half2_rn(eW[t * EF + k]);
    __half2 bias2 = __float2half2_rn(eB[t]);

    for (int i = t; i < 32 * EF; i += 128) {
        int pr = i / EF, k = i % EF;
        size_t e0 = (size_t)(base + 2 * pr) * EF + k;
        es2[i] = __floats2half2_rn(ea[e0], ea[e0 + EF]);
    }
    __syncthreads();

#pragma unroll 4
    for (int pr = 0; pr < 32; pr++) {
        __half2 acc = bias2;
#pragma unroll
        for (int k = 0; k < EF; k++) acc = __hfma2(w2[k], es2[pr * EF + k], acc);
        g_e[(size_t)pos[2 * pr] * HH + t]     = __low2half(acc);
        g_e[(size_t)pos[2 * pr + 1] * HH + t] = __high2half(acc);
    }
}

// ---------------- launch #4 (PROFILED): streaming GINE aggregation ----------
// z16 = fp16(h + sum relu(h16[src] + e)); 4-edge unroll, 4 acc chains.
__device__ __forceinline__ float4 half4_to_float4(uint2 v) {
    __half2 p0 = *reinterpret_cast<__half2*>(&v.x);
    __half2 p1 = *reinterpret_cast<__half2*>(&v.y);
    float2 f0 = __half22float2(p0);
    float2 f1 = __half22float2(p1);
    return make_float4(f0.x, f0.y, f1.x, f1.y);
}
__device__ __forceinline__ void acc_relu(float4& a, float4 h, float4 e) {
    a.x += fmaxf(h.x + e.x, 0.f);
    a.y += fmaxf(h.y + e.y, 0.f);
    a.z += fmaxf(h.z + e.z, 0.f);
    a.w += fmaxf(h.w + e.w, 0.f);
}

__global__ void __launch_bounds__(256) aggregate_kernel() {
    int gid = blockIdx.x * blockDim.x + threadIdx.x;
    int node = gid >> 5;
    if (node >= NN) return;
    int lane = gid & 31;
    const float4* hp = (const float4*)g_h;
    const uint2* hp16 = (const uint2*)g_h16;   // 4 halfs per lane
    const uint2* ep = (const uint2*)g_e;
    float4 a0 = make_float4(0.f, 0.f, 0.f, 0.f);
    float4 a1 = make_float4(0.f, 0.f, 0.f, 0.f);
    float4 a2 = make_float4(0.f, 0.f, 0.f, 0.f);
    float4 a3 = make_float4(0.f, 0.f, 0.f, 0.f);
    int beg = g_row[node], end = g_row[node + 1];
    int i = beg;
    for (; i + 4 <= end; i += 4) {
        int s0 = __ldg(&g_src[i]);
        int s1 = __ldg(&g_src[i + 1]);
        int s2 = __ldg(&g_src[i + 2]);
        int s3 = __ldg(&g_src[i + 3]);
        float4 e0 = half4_to_float4(ep[(size_t)i * 32 + lane]);
        float4 e1 = half4_to_float4(ep[(size_t)(i + 1) * 32 + lane]);
        float4 e2 = half4_to_float4(ep[(size_t)(i + 2) * 32 + lane]);
        float4 e3 = half4_to_float4(ep[(size_t)(i + 3) * 32 + lane]);
        float4 h0 = half4_to_float4(hp16[s0 * 32 + lane]);
        float4 h1 = half4_to_float4(hp16[s1 * 32 + lane]);
        float4 h2 = half4_to_float4(hp16[s2 * 32 + lane]);
        float4 h3 = half4_to_float4(hp16[s3 * 32 + lane]);
        acc_relu(a0, h0, e0);
        acc_relu(a1, h1, e1);
        acc_relu(a2, h2, e2);
        acc_relu(a3, h3, e3);
    }
    for (; i < end; i++) {
        int s0 = __ldg(&g_src[i]);
        float4 e0 = half4_to_float4(ep[(size_t)i * 32 + lane]);
        float4 h0 = half4_to_float4(hp16[s0 * 32 + lane]);
        acc_relu(a0, h0, e0);
    }
    float4 hv = hp[node * 32 + lane];       // self term fp32
    a0.x += a1.x + a2.x + a3.x + hv.x;
    a0.y += a1.y + a2.y + a3.y + hv.y;
    a0.z += a1.z + a2.z + a3.z + hv.z;
    a0.w += a1.w + a2.w + a3.w + hv.w;
    __half2 z0 = __floats2half2_rn(a0.x, a0.y);
    __half2 z1 = __floats2half2_rn(a0.z, a0.w);
    uint2 u;
    u.x = *reinterpret_cast<uint32_t*>(&z0);
    u.y = *reinterpret_cast<uint32_t*>(&z1);
    ((uint2*)g_z16)[node * 32 + lane] = u;
}

// ---------------- fused HMMA MLP: lin1+BN+relu+lin2+relu+residual -----------
// 128x128 tile, K=128, fp16 in / fp32 acc. Intermediate lives in AS smem.
// Inputs (z, W1, W2) are all pre-converted fp16 -> staging is pure copies.
#define LDA 136
#define GEMM_SMEM_BYTES (3 * 128 * LDA * 2)   // 104448

// stage fp16 source (rows guarded) into padded smem tile, uint4 = 8 halfs
__device__ __forceinline__ void stage_f16(const __half* __restrict__ src,
                                          __half* dst, int rowbase, int t,
                                          bool guard) {
    const uint4* s4 = (const uint4*)src;
    for (int idx = t; idx < 128 * 16; idx += 256) {
        int m = idx >> 4, q = idx & 15;
        int row = rowbase + m;
        uint4 v = make_uint4(0u, 0u, 0u, 0u);
        if (!guard || row < NN) v = s4[row * 16 + q];
        *(uint4*)&dst[m * LDA + 8 * q] = v;
    }
}

// warp-level mma mainloop: 8 warps as 4(m) x 2(n); warp tile 32x64
__device__ __forceinline__ void hmma_main(const __half* AS, const __half* WS,
                                          int t, float acc[2][8][4]) {
    int lane = t & 31, warp = t >> 5;
    int mbase = (warp & 3) * 32;
    int nbase = (warp >> 2) * 64;

    uint32_t a_addr[2], b_addr[8];
#pragma unroll
    for (int mt = 0; mt < 2; mt++) {
        int row = mbase + mt * 16 + (lane & 15);
        int col = (lane >> 4) * 8;
        a_addr[mt] = smem_u32(&AS[row * LDA + col]);
    }
#pragma unroll
    for (int nt = 0; nt < 8; nt++) {
        int n = nbase + nt * 8 + (lane & 7);
        int col = ((lane >> 3) & 1) * 8;
        b_addr[nt] = smem_u32(&WS[n * LDA + col]);
    }

#pragma unroll
    for (int ks = 0; ks < 8; ks++) {
        uint32_t koff = ks * 32;            // 16 halfs = 32 bytes
        uint32_t a[2][4], b[8][2];
#pragma unroll
        for (int mt = 0; mt < 2; mt++)
            ldsm_x4(a_addr[mt] + koff, a[mt][0], a[mt][1], a[mt][2], a[mt][3]);
#pragma unroll
        for (int nt = 0; nt < 8; nt++)
            ldsm_x2(b_addr[nt] + koff, b[nt][0], b[nt][1]);
#pragma unroll
        for (int mt = 0; mt < 2; mt++)
#pragma unroll
            for (int nt = 0; nt < 8; nt++)
                mma16816(acc[mt][nt], a[mt][0], a[mt][1], a[mt][2], a[mt][3],
                         b[nt][0], b[nt][1]);
    }
}

__global__ void __launch_bounds__(256) mlp_kernel(const float* __restrict__ b2,
                                                  int li) {
    extern __shared__ __half smh[];
    __half* AS  = smh;
    __half* WS  = smh + 128 * LDA;
    __half* WS2 = smh + 2 * 128 * LDA;
    int t = threadIdx.x;
    int rowbase = blockIdx.x * 128;

    stage_f16(g_z16, AS, rowbase, t, true);
    stage_f16(g_w16 + (li * 2 + 0) * HH * HH, WS, 0, t, false);
    stage_f16(g_w16 + (li * 2 + 1) * HH * HH, WS2, 0, t, false);
    __syncthreads();

    float acc[2][8][4];
#pragma unroll
    for (int mt = 0; mt < 2; mt++)
#pragma unroll
        for (int nt = 0; nt < 8; nt++)
#pragma unroll
            for (int i = 0; i < 4; i++) acc[mt][nt][i] = 0.f;

    hmma_main(AS, WS, t, acc);
    __syncthreads();   // all reads of AS done before rewrite

    // epilogue 1: BN(folded)+relu -> fp16 back into AS
    int lane = t & 31, warp = t >> 5;
    int mbase = (warp & 3) * 32;
    int nbase = (warp >> 2) * 64;
    int gr = lane >> 2;          // 0..7
    int gc2 = (lane & 3) * 2;    // 0,2,4,6
#pragma unroll
    for (int nt = 0; nt < 8; nt++) {
        int col = nbase + nt * 8 + gc2;
        float sc0 = g_scale[li * HH + col],     sh0 = g_shift[li * HH + col];
        float sc1 = g_scale[li * HH + col + 1], sh1 = g_shift[li * HH + col + 1];
#pragma unroll
        for (int mt = 0; mt < 2; mt++) {
            int m0 = mbase + mt * 16 + gr;
            float v0 = fmaxf(fmaf(acc[mt][nt][0], sc0, sh0), 0.f);
            float v1 = fmaxf(fmaf(acc[mt][nt][1], sc1, sh1), 0.f);
            *(__half2*)&AS[m0 * LDA + col] = __floats2half2_rn(v0, v1);
            float v2 = fmaxf(fmaf(acc[mt][nt][2], sc0, sh0), 0.f);
            float v3 = fmaxf(fmaf(acc[mt][nt][3], sc1, sh1), 0.f);
            *(__half2*)&AS[(m0 + 8) * LDA + col] = __floats2half2_rn(v2, v3);
        }
    }
    __syncthreads();

#pragma unroll
    for (int mt = 0; mt < 2; mt++)
#pragma unroll
        for (int nt = 0; nt < 8; nt++)
#pragma unroll
            for (int i = 0; i < 4; i++) acc[mt][nt][i] = 0.f;

    hmma_main(AS, WS2, t, acc);

    // epilogue 2: relu + residual into g_h (fp32) and g_h16 mirror
#pragma unroll
    for (int nt = 0; nt < 8; nt++) {
        int col = nbase + nt * 8 + gc2;
        float b0 = b2[col], b1 = b2[col + 1];
#pragma unroll
        for (int mt = 0; mt < 2; mt++) {
            int r0 = rowbase + mbase + mt * 16 + gr;
            if (r0 < NN) {
                float2 h = *(float2*)&g_h[r0 * HH + col];
                h.x += fmaxf(acc[mt][nt][0] + b0, 0.f);
                h.y += fmaxf(acc[mt][nt][1] + b1, 0.f);
                *(float2*)&g_h[r0 * HH + col] = h;
                *(__half2*)&g_h16[r0 * HH + col] = __floats2half2_rn(h.x, h.y);
            }
            int r1 = r0 + 8;
            if (r1 < NN) {
                float2 h = *(float2*)&g_h[r1 * HH + col];
                h.x += fmaxf(acc[mt][nt][2] + b0, 0.f);
                h.y += fmaxf(acc[mt][nt][3] + b1, 0.f);
                *(float2*)&g_h[r1 * HH + col] = h;
                *(__half2*)&g_h16[r1 * HH + col] = __floats2half2_rn(h.x, h.y);
            }
        }
    }
}

// ---------------- pooling ----------------------------------------------------
__global__ void __launch_bounds__(128) pool_kernel(const int* __restrict__ batch) {
    int t = threadIdx.x;
    int base = blockIdx.x * 128;
    float acc = 0.f, runc = 0.f;
    int cur = -1;
    for (int j = 0; j < 128; j++) {
        int node = base + j;
        if (node >= NN) break;
        int g = batch[node];
        if (g != cur) {
            if (cur >= 0) {
                atomicAdd(&g_pool[cur * 128 + t], acc);
                if (t == 0) atomicAdd(&g_gcnt[cur], runc);
            }
            cur = g; acc = 0.f; runc = 0.f;
        }
        acc += g_h[node * 128 + t];
        runc += 1.f;
    }
    if (cur >= 0) {
        atomicAdd(&g_pool[cur * 128 + t], acc);
        if (t == 0) atomicAdd(&g_gcnt[cur], runc);
    }
}

// ---------------- final projection ------------------------------------------
__global__ void __launch_bounds__(128) proj_kernel(const float* __restrict__ pW,
                                                   const float* __restrict__ pb,
                                                   float* __restrict__ out) {
    __shared__ float pr[128];
    int g = blockIdx.x, t = threadIdx.x;
    float c = fmaxf(g_gcnt[g], 1.f);
    pr[t] = g_pool[g * 128 + t] / c;
    __syncthreads();
    float acc = pb[t];
#pragma unroll 4
    for (int h = 0; h < 128; h++) acc = fmaf(pr[h], pW[t * 128 + h], acc);
    out[g * 128 + t] = acc;
}

// ---------------- cleanup: restore zero-invariant for next call -------------
__global__ void __launch_bounds__(256) cleanup_kernel() {
    int i = blockIdx.x * blockDim.x + threadIdx.x;
    if (i < NN) g_cnt[i] = 0;
    if (i < NG * HH) g_pool[i] = 0.f;
    if (i < NG) g_gcnt[i] = 0.f;
}

// ---------------- launch ------------------------------------------------------
extern "C" void kernel_launch(void* const* d_in, const int* in_sizes, int n_in,
                              void* d_out, int out_size) {
    const float* x       = (const float*)d_in[0];
    const int*   ei      = (const int*)  d_in[1];
    const float* ea      = (const float*)d_in[2];
    const int*   batch   = (const int*)  d_in[3];
    const float* node_W  = (const float*)d_in[4];
    const float* node_b  = (const float*)d_in[5];
    const float* edge_W  = (const float*)d_in[6];
    const float* edge_b  = (const float*)d_in[7];
    const float* lin1_W  = (const float*)d_in[8];
    const float* lin1_b  = (const float*)d_in[9];
    const float* bn_g    = (const float*)d_in[10];
    const float* bn_b    = (const float*)d_in[11];
    const float* bn_m    = (const float*)d_in[12];
    const float* bn_v    = (const float*)d_in[13];
    const float* lin2_W  = (const float*)d_in[14];
    const float* lin2_b  = (const float*)d_in[15];
    const float* proj_W  = (const float*)d_in[16];
    const float* proj_b  = (const float*)d_in[17];
    float* out = (float*)d_out;

    static bool attr_done = false;
    if (!attr_done) {
        cudaFuncSetAttribute(mlp_kernel,
                             cudaFuncAttributeMaxDynamicSharedMemorySize,
                             GEMM_SMEM_BYTES);
        attr_done = true;
    }

    fused_front<<<FUSED_GRID, 128>>>(x, node_W, node_b, ei,
                                     lin1_b, bn_g, bn_b, bn_m, bn_v,
                                     lin1_W, lin2_W);
    scan_kernel<<<1, 1024>>>();
    edge_embed<<<NE / 64, 128>>>(ei, ea, edge_W, edge_b);

    const int gemm_grid = (NN + 127) / 128;
    for (int li = 0; li < NL; li++) {
        // #4 (li==0) -> profiled: verify 4-unroll + fp16-z store (~48-50us)
        aggregate_kernel<<<(NN * 32 + 255) / 256, 256>>>();
        mlp_kernel<<<gemm_grid, 256, GEMM_SMEM_BYTES>>>(lin2_b + li * HH, li);
    }

    pool_kernel<<<(NN + 127) / 128, 128>>>(batch);
    proj_kernel<<<NG, 128>>>(proj_W, proj_b, out);
    cleanup_kernel<<<(NN + 255) / 256, 256>>>();
}